// round 12
// baseline (speedup 1.0000x reference)
#include <cuda_runtime.h>
#include <cuda_bf16.h>
#include <cuda_fp16.h>
#include <cstdint>
#include <math.h>

#define S_LEN 2048
#define HID   2048
#define NH    32
#define NKV   4
#define HD    128
#define NQ    (NH * HD)    // 4096
#define NKVD  (NKV * HD)   // 512
#define NQKV  (NQ + 2 * NKVD)  // 5120

// ---------------------------------------------------------------------------
// Scratch (device globals — no allocation allowed)
// ---------------------------------------------------------------------------
__device__ __half g_x16[S_LEN * HID];
__device__ __half g_wqkvT[NQKV * HID];   // fp16 weights, [N][K]
__device__ __half g_woT[HID * NQ];
__device__ __half g_at16[S_LEN * NQ];

__device__ __half g_q16h[S_LEN * NQ];
__device__ __half g_q16l[S_LEN * NQ];
__device__ __half g_k16h[S_LEN * NKVD];
__device__ __half g_v16[S_LEN * NKVD];

// ---------------------------------------------------------------------------
// helpers
// ---------------------------------------------------------------------------
__device__ __forceinline__ uint32_t smem_u32(const void* p) {
    uint32_t a;
    asm("{ .reg .u64 t; cvta.to.shared.u64 t, %1; cvt.u32.u64 %0, t; }"
        : "=r"(a) : "l"(p));
    return a;
}

__device__ __forceinline__ void cpa16(uint32_t dst, const void* src) {
    asm volatile(
        "{\n\t.reg .u64 g;\n\tcvta.to.global.u64 g, %1;\n\t"
        "cp.async.cg.shared.global [%0], [g], 16;\n\t}"
        :: "r"(dst), "l"(src) : "memory");
}
#define CPA_COMMIT() asm volatile("cp.async.commit_group;" ::: "memory")
#define CPA_WAIT1()  asm volatile("cp.async.wait_group 1;" ::: "memory")
#define CPA_WAIT0()  asm volatile("cp.async.wait_group 0;" ::: "memory")

#define LDSM4(r, addr) \
    asm volatile("ldmatrix.sync.aligned.m8n8.x4.shared.b16 {%0,%1,%2,%3}, [%4];" \
        : "=r"((r)[0]), "=r"((r)[1]), "=r"((r)[2]), "=r"((r)[3]) : "r"(addr))

__device__ __forceinline__ void mma16816f(float* d, const uint32_t* a,
                                          uint32_t b0, uint32_t b1) {
    asm volatile(
        "mma.sync.aligned.m16n8k16.row.col.f32.f16.f16.f32 "
        "{%0,%1,%2,%3}, {%4,%5,%6,%7}, {%8,%9}, {%0,%1,%2,%3};"
        : "+f"(d[0]), "+f"(d[1]), "+f"(d[2]), "+f"(d[3])
        : "r"(a[0]), "r"(a[1]), "r"(a[2]), "r"(a[3]), "r"(b0), "r"(b1));
}

// Fast exp on the FFMA pipe. Rel err < 3e-6 on [-87, 0].
__device__ __forceinline__ float fexp(float x) {
    x = fmaxf(x, -87.0f);
    float z  = fmaf(x, 1.44269504089f, 12582912.0f);
    float nf = z - 12582912.0f;
    float f  = fmaf(x, 1.44269504089f, -nf);
    float p  = 1.333355815e-3f;
    p = fmaf(p, f, 9.618129107e-3f);
    p = fmaf(p, f, 5.550410866e-2f);
    p = fmaf(p, f, 2.402265069e-1f);
    p = fmaf(p, f, 6.931471806e-1f);
    p = fmaf(p, f, 1.0f);
    int n = __float_as_int(z) - 0x4B400000;
    return __int_as_float(__float_as_int(p) + (n << 23));
}

// ---------------------------------------------------------------------------
// aux kernels
// ---------------------------------------------------------------------------
__global__ void cvt_f16v(const float4* __restrict__ in,
                         uint2* __restrict__ o, int n4)
{
    int i = blockIdx.x * blockDim.x + threadIdx.x;
    if (i < n4) {
        float4 v = in[i];
        __half2 a = __halves2half2(__float2half(v.x), __float2half(v.y));
        __half2 b = __halves2half2(__float2half(v.z), __float2half(v.w));
        uint2 r;
        r.x = *(uint32_t*)&a; r.y = *(uint32_t*)&b;
        o[i] = r;
    }
}

// Transpose [R][C] fp32 -> [C][R] fp16
__global__ void transpose_f16(const float* __restrict__ in,
                              __half* __restrict__ o, int R, int C)
{
    __shared__ float t[32][33];
    int c0 = blockIdx.x << 5, r0 = blockIdx.y << 5;
    int x = threadIdx.x, y = threadIdx.y;
#pragma unroll
    for (int j = y; j < 32; j += 8)
        t[j][x] = in[(size_t)(r0 + j) * C + c0 + x];
    __syncthreads();
#pragma unroll
    for (int j = y; j < 32; j += 8)
        o[(size_t)(c0 + j) * R + r0 + x] = __float2half(t[x][j]);
}

// ---------------------------------------------------------------------------
// GEMM mainloop shared macro bits: CTA 128x128, 8 warps (2x4), warp 64x32,
// K chunks of 32, 3-stage cp.async, one __syncthreads per chunk.
// ---------------------------------------------------------------------------
#define RPAD_B 80
#define TILE_B (128 * RPAD_B)            // 10240
#define STG_B  (2 * TILE_B)              // 20480: A, B
#define GEMM_SMEM (3 * STG_B)            // 61440 (2 CTAs/SM)

#define GEMM_MAINLOOP(Aptr, Bptr, Kdim)                                        \
    float acc[4][4][4];                                                        \
    _Pragma("unroll")                                                          \
    for (int i = 0; i < 4; i++)                                                \
        _Pragma("unroll")                                                      \
        for (int j = 0; j < 4; j++)                                            \
            _Pragma("unroll")                                                  \
            for (int r = 0; r < 4; r++) acc[i][j][r] = 0.0f;                   \
    const uint32_t lrow = lane & 15;                                           \
    const uint32_t lkof = (lane >> 4) << 4;                                    \
    const __half* gb[2] = {Aptr, Bptr};                                        \
    const int gr0[2] = {m0, n0};                                               \
    const int nck = (Kdim) >> 5;                                               \
    auto load_stage = [&](int ck, int st) {                                    \
        const int k0 = ck << 5;                                                \
        const uint32_t sb = sbase + st * STG_B;                                \
        _Pragma("unroll")                                                      \
        for (int t = 0; t < 2; t++) {                                          \
            _Pragma("unroll")                                                  \
            for (int i = 0; i < 2; i++) {                                      \
                int idx = (i << 8) + tid;                                      \
                int row = idx >> 2, c = idx & 3;                               \
                cpa16(sb + t * TILE_B + row * RPAD_B + c * 16,                 \
                      gb[t] + (size_t)(gr0[t] + row) * (Kdim) + k0 + c * 8);   \
            }                                                                  \
        }                                                                      \
        CPA_COMMIT();                                                          \
    };                                                                         \
    load_stage(0, 0);                                                          \
    load_stage(1, 1);                                                          \
    int stg = 0;                                                               \
    for (int ck = 0; ck < nck; ck++) {                                         \
        if (ck + 1 < nck) { CPA_WAIT1(); } else { CPA_WAIT0(); }               \
        __syncthreads();                                                       \
        if (ck + 2 < nck) {                                                    \
            int s2 = stg + 2; if (s2 >= 3) s2 -= 3;                            \
            load_stage(ck + 2, s2);                                            \
        }                                                                      \
        const uint32_t sb = sbase + stg * STG_B;                               \
        const uint32_t ab = sb + (wm * 64 + lrow) * RPAD_B + lkof;             \
        const uint32_t bb = sb + TILE_B + (wn * 32 + lrow) * RPAD_B + lkof;    \
        _Pragma("unroll")                                                      \
        for (int kk = 0; kk < 2; kk++) {                                       \
            const uint32_t ko = kk * 32;                                       \
            uint32_t bh[2][4];                                                 \
            _Pragma("unroll")                                                  \
            for (int np = 0; np < 2; np++)                                     \
                LDSM4(bh[np], bb + np * 16 * RPAD_B + ko);                     \
            _Pragma("unroll")                                                  \
            for (int mt = 0; mt < 4; mt++) {                                   \
                uint32_t ah[4];                                                \
                LDSM4(ah, ab + mt * 16 * RPAD_B + ko);                         \
                _Pragma("unroll")                                              \
                for (int nt = 0; nt < 4; nt++) {                               \
                    const int np = nt >> 1, sl = nt & 1;                       \
                    mma16816f(acc[mt][nt], ah, bh[np][sl], bh[np][sl + 2]);    \
                }                                                              \
            }                                                                  \
        }                                                                      \
        if (++stg >= 3) stg -= 3;                                              \
    }

// ---------------------------------------------------------------------------
// Plain fp16 GEMM (out projection): fp32 output
// ---------------------------------------------------------------------------
__global__ void __launch_bounds__(256, 2) gemm_mma_f16(
    const __half* __restrict__ A, const __half* __restrict__ B,
    float* __restrict__ C, int N, int K)
{
    extern __shared__ char smraw[];
    const int tid  = threadIdx.x;
    const int wid  = tid >> 5, lane = tid & 31;
    const int m0 = blockIdx.y << 7, n0 = blockIdx.x << 7;
    const int wm = wid >> 2;
    const int wn = wid & 3;
    const uint32_t sbase = smem_u32(smraw);

    GEMM_MAINLOOP(A, B, K)

    const int erow = (lane >> 2);
    const int ecol = (lane & 3) << 1;
#pragma unroll
    for (int mt = 0; mt < 4; mt++) {
#pragma unroll
        for (int nt = 0; nt < 4; nt++) {
            const int r = m0 + wm * 64 + mt * 16 + erow;
            const int c = n0 + wn * 32 + nt * 8 + ecol;
            *(float2*)(C + (size_t)r * N + c) =
                make_float2(acc[mt][nt][0], acc[mt][nt][1]);
            *(float2*)(C + (size_t)(r + 8) * N + c) =
                make_float2(acc[mt][nt][2], acc[mt][nt][3]);
        }
    }
}

// ---------------------------------------------------------------------------
// Fused QKV GEMM: mainloop + fused RMSNorm+RoPE epilogue.
// Each CTA's N-tile (128 cols) = exactly one head's 128 dims; rows = seq.
// Q cols -> rmsnorm+rope -> q16h/q16l. K cols -> rmsnorm+rope -> k16h.
// V cols -> fp16 v16. No fp32 intermediate.
// ---------------------------------------------------------------------------
__global__ void __launch_bounds__(256, 2) gemm_qkv_fused(
    const __half* __restrict__ A, const __half* __restrict__ B,
    const float* __restrict__ qn, const float* __restrict__ kn,
    const float* __restrict__ cs, const float* __restrict__ sn,
    __half* __restrict__ q16h, __half* __restrict__ q16l,
    __half* __restrict__ k16h, __half* __restrict__ v16)
{
    extern __shared__ char smraw[];
    const int tid  = threadIdx.x;
    const int wid  = tid >> 5, lane = tid & 31;
    const int m0 = blockIdx.y << 7, n0 = blockIdx.x << 7;
    const int wm = wid >> 2;
    const int wn = wid & 3;
    const uint32_t sbase = smem_u32(smraw);

    GEMM_MAINLOOP(A, B, HID)

    const int erow = (lane >> 2);
    const int ecol = (lane & 3) << 1;

    __syncthreads();   // mainloop smem reads done before stage reuse

    if (n0 >= NQ + NKVD) {
        // V: direct fp16 store
        const int hc0 = n0 - (NQ + NKVD);
#pragma unroll
        for (int mt = 0; mt < 4; mt++) {
#pragma unroll
            for (int nt = 0; nt < 4; nt++) {
                const int r = m0 + wm * 64 + mt * 16 + erow;
                const int c = hc0 + wn * 32 + nt * 8 + ecol;
                __half2 v0 = __halves2half2(__float2half(acc[mt][nt][0]),
                                            __float2half(acc[mt][nt][1]));
                __half2 v1 = __halves2half2(__float2half(acc[mt][nt][2]),
                                            __float2half(acc[mt][nt][3]));
                *(__half2*)(v16 + (size_t)r * NKVD + c)       = v0;
                *(__half2*)(v16 + (size_t)(r + 8) * NKVD + c) = v1;
            }
        }
        return;
    }

    // Q or K: fused rmsnorm + rope, two 64-row passes through smem stage
    const bool isQ = (n0 < NQ);
    const float* wvec = isQ ? qn : kn;
    const int hc0  = isQ ? n0 : (n0 - NQ);
    const int outW = isQ ? NQ : NKVD;
    float* stage = (float*)smraw;          // 64 x 132 fp32 = 33792 B

    for (int half = 0; half < 2; half++) {
        if (wm == half) {
#pragma unroll
            for (int mt = 0; mt < 4; mt++) {
#pragma unroll
                for (int nt = 0; nt < 4; nt++) {
                    const int sr = mt * 16 + erow;
                    const int sc = wn * 32 + nt * 8 + ecol;
                    stage[sr * 132 + sc]           = acc[mt][nt][0];
                    stage[sr * 132 + sc + 1]       = acc[mt][nt][1];
                    stage[(sr + 8) * 132 + sc]     = acc[mt][nt][2];
                    stage[(sr + 8) * 132 + sc + 1] = acc[mt][nt][3];
                }
            }
        }
        __syncthreads();

        {
            const int rr = tid >> 2;              // 0..63
            const int cc = (tid & 3) << 5;        // 0,32,64,96
            const int sg = m0 + half * 64 + rr;   // global seq index
            const float* row = stage + rr * 132;

            float ss = 0.0f;
#pragma unroll
            for (int j = 0; j < 32; j += 4) {
                float4 v = *(const float4*)(row + cc + j);
                ss += v.x * v.x + v.y * v.y + v.z * v.z + v.w * v.w;
            }
            ss += __shfl_xor_sync(0xffffffffu, ss, 1);
            ss += __shfl_xor_sync(0xffffffffu, ss, 2);
            const float inv = rsqrtf(ss * (1.0f / 128.0f) + 1e-6f);

#pragma unroll
            for (int j = 0; j < 32; j++) {
                const int d  = cc + j;
                const int pd = (d < 64) ? d + 64 : d - 64;
                float xn = row[d]  * inv * wvec[d];
                float xp = row[pd] * inv * wvec[pd];
                float rot = (d < 64) ? -xp : xp;
                float res = xn * cs[sg * HD + d] + rot * sn[sg * HD + d];
                __half hh = __float2half(res);
                const size_t o = (size_t)sg * outW + hc0 + d;
                if (isQ) {
                    q16h[o] = hh;
                    q16l[o] = __float2half(res - __half2float(hh));
                } else {
                    k16h[o] = hh;
                }
            }
        }
        __syncthreads();
    }
}

// ---------------------------------------------------------------------------
// Tensor-core flash attention, double-buffered K/V prefetch (R8 proven).
// ---------------------------------------------------------------------------
#include <mma.h>
using namespace nvcuda;

#define QLD 136
#define SLD 132
#define PLD 72

#define OFF_QH 0
#define OFF_QL 17408
#define OFF_KV 34816          // per-buf: KH +0, V +17408
#define KVBUF  34816
#define OFF_S  104448
#define OFF_P  138240
#define OFF_O  147456
#define OFF_M  180224
#define OFF_L  180480
#define OFF_AL 180736
#define FLASH_SMEM 180992

__global__ void __launch_bounds__(256) flash_wmma(
    const __half* __restrict__ qh, const __half* __restrict__ ql,
    const __half* __restrict__ kh, const __half* __restrict__ vv,
    __half* __restrict__ attn)
{
    extern __shared__ char smc[];
    __half* sQh = (__half*)(smc + OFF_QH);
    __half* sQl = (__half*)(smc + OFF_QL);
    float*  sS  = (float*)(smc + OFF_S);
    __half* sP  = (__half*)(smc + OFF_P);
    float*  sO  = (float*)(smc + OFF_O);
    float*  sM  = (float*)(smc + OFF_M);
    float*  sL  = (float*)(smc + OFF_L);
    float*  sA  = (float*)(smc + OFF_AL);

    const int h     = blockIdx.x;
    const int ptile = (int)gridDim.y - 1 - blockIdx.y;
    const int m0    = ptile << 6;
    const int kvh   = h >> 3;
    const int tid   = threadIdx.x;
    const int wid   = tid >> 5;
    const int rs    = wid >> 1;
    const int ch    = wid & 1;
    const float scale = 0.08838834764831845f;

    auto load_kv = [&](int kb, int buf) {
        const int k0g = kb << 6;
        const uint32_t base = smem_u32(smc) + OFF_KV + buf * KVBUF;
#pragma unroll
        for (int i = 0; i < 4; i++) {
            int idx = tid + (i << 8);
            int r = idx >> 4, c = idx & 15;
            size_t so = (size_t)(k0g + r) * NKVD + kvh * HD + (c << 3);
            uint32_t off = r * (QLD * 2) + (c << 4);
            cpa16(base + off,         kh + so);
            cpa16(base + 17408 + off, vv + so);
        }
        CPA_COMMIT();
    };

    {
        uint32_t dqh = smem_u32(sQh), dql = smem_u32(sQl);
#pragma unroll
        for (int i = 0; i < 4; i++) {
            int idx = tid + (i << 8);
            int r = idx >> 4, c = idx & 15;
            size_t so = (size_t)(m0 + r) * NQ + h * HD + (c << 3);
            uint32_t off = r * (QLD * 2) + (c << 4);
            cpa16(dqh + off, qh + so);
            cpa16(dql + off, ql + so);
        }
        CPA_COMMIT();
    }
    load_kv(0, 0);

    for (int i = tid; i < 64 * 128 / 4; i += 256)
        ((float4*)sO)[i] = make_float4(0.f, 0.f, 0.f, 0.f);
    if (tid < 64) { sM[tid] = -1e30f; sL[tid] = 0.f; }

    for (int kb = 0; kb <= ptile; kb++) {
        const int k0g = kb << 6;
        const int buf = kb & 1;
        __half* sKh = (__half*)(smc + OFF_KV + buf * KVBUF);
        __half* sV  = (__half*)(smc + OFF_KV + buf * KVBUF + 17408);

        if (kb < ptile) { load_kv(kb + 1, buf ^ 1); CPA_WAIT1(); }
        else            { CPA_WAIT0(); }
        __syncthreads();

        {
            wmma::fragment<wmma::accumulator, 16, 16, 16, float> accS[2];
            wmma::fill_fragment(accS[0], 0.0f);
            wmma::fill_fragment(accS[1], 0.0f);
#pragma unroll
            for (int k0 = 0; k0 < 128; k0 += 16) {
                wmma::fragment<wmma::matrix_a, 16, 16, 16, __half, wmma::row_major> ah, al;
                wmma::load_matrix_sync(ah, sQh + rs * 16 * QLD + k0, QLD);
                wmma::load_matrix_sync(al, sQl + rs * 16 * QLD + k0, QLD);
#pragma unroll
                for (int j = 0; j < 2; j++) {
                    wmma::fragment<wmma::matrix_b, 16, 16, 16, __half, wmma::col_major> bh;
                    int kcol = ch * 32 + j * 16;
                    wmma::load_matrix_sync(bh, sKh + kcol * QLD + k0, QLD);
                    wmma::mma_sync(accS[j], ah, bh, accS[j]);
                    wmma::mma_sync(accS[j], al, bh, accS[j]);
                }
            }
#pragma unroll
            for (int j = 0; j < 2; j++)
                wmma::store_matrix_sync(sS + rs * 16 * SLD + ch * 32 + j * 16,
                                        accS[j], SLD, wmma::mem_row_major);
        }
        __syncthreads();

        {
            const int r  = tid >> 2;
            const int q4 = tid & 3;
            float* srow = sS + r * SLD + q4 * 16;
            const int qglob = m0 + r;
            const int kbase = k0g + q4 * 16;

            float vals[16];
            float mx = -1e30f;
#pragma unroll
            for (int j = 0; j < 16; j++) {
                float s = srow[j];
                s = (kbase + j <= qglob) ? s * scale : -1e30f;
                vals[j] = s;
                mx = fmaxf(mx, s);
            }
            mx = fmaxf(mx, __shfl_xor_sync(0xffffffffu, mx, 1));
            mx = fmaxf(mx, __shfl_xor_sync(0xffffffffu, mx, 2));

            float mold = sM[r];
            float mnew = fmaxf(mold, mx);
            float alpha = fexp(mold - mnew);

            __half* prow = sP + r * PLD + q4 * 16;
            float lsum = 0.f;
#pragma unroll
            for (int j = 0; j < 16; j++) {
                float p = fexp(vals[j] - mnew);
                prow[j] = __float2half(p);
                lsum += p;
            }
            lsum += __shfl_xor_sync(0xffffffffu, lsum, 1);
            lsum += __shfl_xor_sync(0xffffffffu, lsum, 2);

            if (q4 == 0) {
                sM[r] = mnew;
                sL[r] = sL[r] * alpha + lsum;
                sA[r] = alpha;
            }
        }
        __syncthreads();

        {
            wmma::fragment<wmma::accumulator, 16, 16, 16, float> accO[4];
#pragma unroll
            for (int j = 0; j < 4; j++) wmma::fill_fragment(accO[j], 0.0f);
#pragma unroll
            for (int k0 = 0; k0 < 64; k0 += 16) {
                wmma::fragment<wmma::matrix_a, 16, 16, 16, __half, wmma::row_major> a;
                wmma::load_matrix_sync(a, sP + rs * 16 * PLD + k0, PLD);
#pragma unroll
                for (int j = 0; j < 4; j++) {
                    wmma::fragment<wmma::matrix_b, 16, 16, 16, __half, wmma::row_major> b;
                    wmma::load_matrix_sync(b, sV + k0 * QLD + ch * 64 + j * 16, QLD);
                    wmma::mma_sync(accO[j], a, b, accO[j]);
                }
            }
#pragma unroll
            for (int j = 0; j < 4; j++)
                wmma::store_matrix_sync(sS + rs * 16 * SLD + ch * 64 + j * 16,
                                        accO[j], SLD, wmma::mem_row_major);
        }
        __syncthreads();

        {
            const int r  = tid >> 2;
            const int c0 = (tid & 3) << 5;
            const float a = sA[r];
            float4* op = (float4*)(sO + r * 128 + c0);
            const float4* pv = (const float4*)(sS + r * SLD + c0);
#pragma unroll
            for (int j = 0; j < 8; j++) {
                float4 o = op[j], p = pv[j];
                o.x = o.x * a + p.x;
                o.y = o.y * a + p.y;
                o.z = o.z * a + p.z;
                o.w = o.w * a + p.w;
                op[j] = o;
            }
        }
        __syncthreads();
    }

    {
        const int r  = tid >> 2;
        const int c0 = (tid & 3) << 5;
        const float inv = 1.0f / sL[r];
        __half* base = attn + (size_t)(m0 + r) * NQ + h * HD + c0;
#pragma unroll
        for (int j = 0; j < 32; j++)
            base[j] = __float2half(sO[r * 128 + c0 + j] * inv);
    }
}

// ---------------------------------------------------------------------------
extern "C" void kernel_launch(void* const* d_in, const int* in_sizes, int n_in,
                              void* d_out, int out_size)
{
    (void)in_sizes; (void)n_in; (void)out_size;
    const float* x  = (const float*)d_in[0];
    const float* wq = (const float*)d_in[1];
    const float* wk = (const float*)d_in[2];
    const float* wv = (const float*)d_in[3];
    const float* wo = (const float*)d_in[4];
    const float* qn = (const float*)d_in[5];
    const float* kn = (const float*)d_in[6];
    const float* cs = (const float*)d_in[7];
    const float* sn = (const float*)d_in[8];
    float* out = (float*)d_out;

    __half *x16, *wT, *woT, *at16;
    cudaGetSymbolAddress((void**)&x16,  g_x16);
    cudaGetSymbolAddress((void**)&wT,   g_wqkvT);
    cudaGetSymbolAddress((void**)&woT,  g_woT);
    cudaGetSymbolAddress((void**)&at16, g_at16);

    __half *q16h, *q16l, *k16h, *v16;
    cudaGetSymbolAddress((void**)&q16h, g_q16h);
    cudaGetSymbolAddress((void**)&q16l, g_q16l);
    cudaGetSymbolAddress((void**)&k16h, g_k16h);
    cudaGetSymbolAddress((void**)&v16,  g_v16);

    cudaFuncSetAttribute(gemm_mma_f16,
                         cudaFuncAttributeMaxDynamicSharedMemorySize, GEMM_SMEM);
    cudaFuncSetAttribute(gemm_qkv_fused,
                         cudaFuncAttributeMaxDynamicSharedMemorySize, GEMM_SMEM);
    cudaFuncSetAttribute(flash_wmma,
                         cudaFuncAttributeMaxDynamicSharedMemorySize, FLASH_SMEM);

    // Convert activations to fp16; transpose weights to fp16 [N][K]
    cvt_f16v<<<(S_LEN * HID / 4 + 255) / 256, 256>>>(
        (const float4*)x, (uint2*)x16, S_LEN * HID / 4);
    transpose_f16<<<dim3(NQ / 32,   HID / 32), dim3(32, 8)>>>(wq, wT, HID, NQ);
    transpose_f16<<<dim3(NKVD / 32, HID / 32), dim3(32, 8)>>>(
        wk, wT + (size_t)NQ * HID, HID, NKVD);
    transpose_f16<<<dim3(NKVD / 32, HID / 32), dim3(32, 8)>>>(
        wv, wT + (size_t)(NQ + NKVD) * HID, HID, NKVD);
    transpose_f16<<<dim3(HID / 32,  NQ / 32),  dim3(32, 8)>>>(wo, woT, NQ, HID);

    // Fused QKV projection + RMSNorm + RoPE + fp16 outputs
    gemm_qkv_fused<<<dim3(NQKV / 128, S_LEN / 128), 256, GEMM_SMEM>>>(
        x16, wT, qn, kn, cs, sn, q16h, q16l, k16h, v16);

    // Flash attention -> fp16
    flash_wmma<<<dim3(NH, S_LEN / 64), 256, FLASH_SMEM>>>(
        q16h, q16l, k16h, v16, at16);

    // Output projection
    gemm_mma_f16<<<dim3(HID / 128, S_LEN / 128), 256, GEMM_SMEM>>>(
        at16, woT, out, HID, NQ);
}

// round 13
// speedup vs baseline: 1.1453x; 1.1453x over previous
#include <cuda_runtime.h>
#include <cuda_bf16.h>
#include <cuda_fp16.h>
#include <cstdint>
#include <math.h>

#define S_LEN 2048
#define HID   2048
#define NH    32
#define NKV   4
#define HD    128
#define NQ    (NH * HD)    // 4096
#define NKVD  (NKV * HD)   // 512
#define NQKV  (NQ + 2 * NKVD)  // 5120

// ---------------------------------------------------------------------------
// Scratch (device globals — no allocation allowed)
// ---------------------------------------------------------------------------
__device__ float g_qkv[S_LEN * NQKV];

__device__ __half g_x16[S_LEN * HID];
__device__ __half g_wqkvT[NQKV * HID];   // fp16 weights, [N][K]
__device__ __half g_woT[HID * NQ];
__device__ __half g_at16[S_LEN * NQ];

__device__ __half g_q16h[S_LEN * NQ];
__device__ __half g_k16h[S_LEN * NKVD];
__device__ __half g_v16[S_LEN * NKVD];

// ---------------------------------------------------------------------------
// helpers
// ---------------------------------------------------------------------------
__device__ __forceinline__ uint32_t smem_u32(const void* p) {
    uint32_t a;
    asm("{ .reg .u64 t; cvta.to.shared.u64 t, %1; cvt.u32.u64 %0, t; }"
        : "=r"(a) : "l"(p));
    return a;
}

__device__ __forceinline__ void cpa16(uint32_t dst, const void* src) {
    asm volatile(
        "{\n\t.reg .u64 g;\n\tcvta.to.global.u64 g, %1;\n\t"
        "cp.async.cg.shared.global [%0], [g], 16;\n\t}"
        :: "r"(dst), "l"(src) : "memory");
}
#define CPA_COMMIT() asm volatile("cp.async.commit_group;" ::: "memory")
#define CPA_WAIT1()  asm volatile("cp.async.wait_group 1;" ::: "memory")
#define CPA_WAIT0()  asm volatile("cp.async.wait_group 0;" ::: "memory")

#define LDSM4(r, addr) \
    asm volatile("ldmatrix.sync.aligned.m8n8.x4.shared.b16 {%0,%1,%2,%3}, [%4];" \
        : "=r"((r)[0]), "=r"((r)[1]), "=r"((r)[2]), "=r"((r)[3]) : "r"(addr))

__device__ __forceinline__ void mma16816f(float* d, const uint32_t* a,
                                          uint32_t b0, uint32_t b1) {
    asm volatile(
        "mma.sync.aligned.m16n8k16.row.col.f32.f16.f16.f32 "
        "{%0,%1,%2,%3}, {%4,%5,%6,%7}, {%8,%9}, {%0,%1,%2,%3};"
        : "+f"(d[0]), "+f"(d[1]), "+f"(d[2]), "+f"(d[3])
        : "r"(a[0]), "r"(a[1]), "r"(a[2]), "r"(a[3]), "r"(b0), "r"(b1));
}

// Fast exp on the FFMA pipe. Rel err < 3e-6 on [-87, 0].
__device__ __forceinline__ float fexp(float x) {
    x = fmaxf(x, -87.0f);
    float z  = fmaf(x, 1.44269504089f, 12582912.0f);
    float nf = z - 12582912.0f;
    float f  = fmaf(x, 1.44269504089f, -nf);
    float p  = 1.333355815e-3f;
    p = fmaf(p, f, 9.618129107e-3f);
    p = fmaf(p, f, 5.550410866e-2f);
    p = fmaf(p, f, 2.402265069e-1f);
    p = fmaf(p, f, 6.931471806e-1f);
    p = fmaf(p, f, 1.0f);
    int n = __float_as_int(z) - 0x4B400000;
    return __int_as_float(__float_as_int(p) + (n << 23));
}

// ---------------------------------------------------------------------------
// aux kernels
// ---------------------------------------------------------------------------
__global__ void cvt_f16v(const float4* __restrict__ in,
                         uint2* __restrict__ o, int n4)
{
    int i = blockIdx.x * blockDim.x + threadIdx.x;
    if (i < n4) {
        float4 v = in[i];
        __half2 a = __halves2half2(__float2half(v.x), __float2half(v.y));
        __half2 b = __halves2half2(__float2half(v.z), __float2half(v.w));
        uint2 r;
        r.x = *(uint32_t*)&a; r.y = *(uint32_t*)&b;
        o[i] = r;
    }
}

__global__ void cvt_v16(const float* __restrict__ qkv, __half* __restrict__ out)
{
    int i = blockIdx.x * blockDim.x + threadIdx.x;
    int s = i >> 9, d = i & 511;
    out[i] = __float2half(qkv[(size_t)s * NQKV + NQ + NKVD + d]);
}

// Transpose [R][C] fp32 -> [C][R] fp16
__global__ void transpose_f16(const float* __restrict__ in,
                              __half* __restrict__ o, int R, int C)
{
    __shared__ float t[32][33];
    int c0 = blockIdx.x << 5, r0 = blockIdx.y << 5;
    int x = threadIdx.x, y = threadIdx.y;
#pragma unroll
    for (int j = y; j < 32; j += 8)
        t[j][x] = in[(size_t)(r0 + j) * C + c0 + x];
    __syncthreads();
#pragma unroll
    for (int j = y; j < 32; j += 8)
        o[(size_t)(c0 + j) * R + r0 + x] = __float2half(t[x][j]);
}

// ---------------------------------------------------------------------------
// Raw-HMMA fp16 GEMM: C[m][n] = sum_k A[m][k] * B[n][k]
// CTA 128x128, 8 warps, warp tile 64x32. K chunks of 32, 3-stage cp.async,
// one __syncthreads per chunk. Smem rows 80 B -> conflict-free ldmatrix.
// ---------------------------------------------------------------------------
#define RPAD_B 80
#define TILE_B (128 * RPAD_B)            // 10240
#define STG_B  (2 * TILE_B)              // 20480: A, B
#define GEMM_SMEM (3 * STG_B)            // 61440 (3 stages, 2 CTAs/SM)

__global__ void __launch_bounds__(256, 2) gemm_mma_f16(
    const __half* __restrict__ A, const __half* __restrict__ B,
    float* __restrict__ C, int N, int K)
{
    extern __shared__ char smraw[];
    const int tid  = threadIdx.x;
    const int wid  = tid >> 5, lane = tid & 31;
    const int m0 = blockIdx.y << 7, n0 = blockIdx.x << 7;
    const int wm = wid >> 2;             // 0..1  (64-row slab)
    const int wn = wid & 3;              // 0..3  (32-col slab)

    const uint32_t sbase = smem_u32(smraw);

    float acc[4][4][4];
#pragma unroll
    for (int i = 0; i < 4; i++)
#pragma unroll
        for (int j = 0; j < 4; j++)
#pragma unroll
            for (int r = 0; r < 4; r++) acc[i][j][r] = 0.0f;

    const uint32_t lrow = lane & 15;
    const uint32_t lkof = (lane >> 4) << 4;

    const __half* gb[2] = {A, B};
    const int gr0[2] = {m0, n0};
    const int nck = K >> 5;

    auto load_stage = [&](int ck, int s) {
        const int k0 = ck << 5;
        const uint32_t sb = sbase + s * STG_B;
#pragma unroll
        for (int t = 0; t < 2; t++) {
#pragma unroll
            for (int i = 0; i < 2; i++) {
                int idx = (i << 8) + tid;          // 0..511
                int row = idx >> 2, c = idx & 3;
                cpa16(sb + t * TILE_B + row * RPAD_B + c * 16,
                      gb[t] + (size_t)(gr0[t] + row) * K + k0 + c * 8);
            }
        }
        CPA_COMMIT();
    };

    load_stage(0, 0);
    load_stage(1, 1);

    int s = 0;
    for (int ck = 0; ck < nck; ck++) {
        if (ck + 1 < nck) { CPA_WAIT1(); } else { CPA_WAIT0(); }
        __syncthreads();
        if (ck + 2 < nck) {
            int s2 = s + 2; if (s2 >= 3) s2 -= 3;
            load_stage(ck + 2, s2);
        }

        const uint32_t sb = sbase + s * STG_B;
        const uint32_t ab = sb + (wm * 64 + lrow) * RPAD_B + lkof;
        const uint32_t bb = sb + TILE_B + (wn * 32 + lrow) * RPAD_B + lkof;

#pragma unroll
        for (int kk = 0; kk < 2; kk++) {
            const uint32_t ko = kk * 32;
            uint32_t bh[2][4];
#pragma unroll
            for (int np = 0; np < 2; np++)
                LDSM4(bh[np], bb + np * 16 * RPAD_B + ko);
#pragma unroll
            for (int mt = 0; mt < 4; mt++) {
                uint32_t ah[4];
                LDSM4(ah, ab + mt * 16 * RPAD_B + ko);
#pragma unroll
                for (int nt = 0; nt < 4; nt++) {
                    const int np = nt >> 1, sl = nt & 1;
                    mma16816f(acc[mt][nt], ah, bh[np][sl], bh[np][sl + 2]);
                }
            }
        }
        if (++s >= 3) s -= 3;
    }

    const int erow = (lane >> 2);
    const int ecol = (lane & 3) << 1;
#pragma unroll
    for (int mt = 0; mt < 4; mt++) {
#pragma unroll
        for (int nt = 0; nt < 4; nt++) {
            const int r = m0 + wm * 64 + mt * 16 + erow;
            const int c = n0 + wn * 32 + nt * 8 + ecol;
            *(float2*)(C + (size_t)r * N + c) =
                make_float2(acc[mt][nt][0], acc[mt][nt][1]);
            *(float2*)(C + (size_t)(r + 8) * N + c) =
                make_float2(acc[mt][nt][2], acc[mt][nt][3]);
        }
    }
}

// ---------------------------------------------------------------------------
// Fused RMSNorm + RoPE, reading a column slice of fused qkv -> fp16
// ---------------------------------------------------------------------------
__global__ __launch_bounds__(128) void rmsnorm_rope_f16(
    const float* __restrict__ qkv, int colOff, const float* __restrict__ w,
    const float* __restrict__ cs, const float* __restrict__ sn, int heads,
    __half* __restrict__ oh)
{
    const int b = blockIdx.x;
    const int s = b / heads;
    const int h = b - s * heads;
    const int d = threadIdx.x;

    const size_t io = (size_t)s * NQKV + colOff + h * HD;
    const size_t oo = ((size_t)s * heads + h) * HD;
    float v = qkv[io + d];

    float ssq = v * v;
#pragma unroll
    for (int off = 16; off > 0; off >>= 1)
        ssq += __shfl_xor_sync(0xffffffffu, ssq, off);

    __shared__ float red[4];
    __shared__ float sh[HD];
    if ((d & 31) == 0) red[d >> 5] = ssq;
    __syncthreads();
    float tot = red[0] + red[1] + red[2] + red[3];

    float xn = v * rsqrtf(tot * (1.0f / HD) + 1e-6f) * w[d];
    sh[d] = xn;
    __syncthreads();

    float partner = (d < 64) ? -sh[d + 64] : sh[d - 64];
    float res = xn * cs[s * HD + d] + partner * sn[s * HD + d];

    oh[oo + d] = __float2half(res);
}

// ---------------------------------------------------------------------------
// Tensor-core flash attention, double-buffered K/V prefetch.
// Q, K, P, V all single fp16; O fp32 smem. Output fp16.
// ---------------------------------------------------------------------------
#include <mma.h>
using namespace nvcuda;

#define QLD 136
#define SLD 132
#define PLD 72

#define OFF_QH 0
#define OFF_KV 17408          // per-buf: KH +0, V +17408
#define KVBUF  34816
#define OFF_S  87040
#define OFF_P  120832
#define OFF_O  130048
#define OFF_M  162816
#define OFF_L  163072
#define OFF_AL 163328
#define FLASH_SMEM 163584

__global__ void __launch_bounds__(256) flash_wmma(
    const __half* __restrict__ qh,
    const __half* __restrict__ kh, const __half* __restrict__ vv,
    __half* __restrict__ attn)
{
    extern __shared__ char smc[];
    __half* sQh = (__half*)(smc + OFF_QH);
    float*  sS  = (float*)(smc + OFF_S);
    __half* sP  = (__half*)(smc + OFF_P);
    float*  sO  = (float*)(smc + OFF_O);
    float*  sM  = (float*)(smc + OFF_M);
    float*  sL  = (float*)(smc + OFF_L);
    float*  sA  = (float*)(smc + OFF_AL);

    const int h     = blockIdx.x;
    const int ptile = (int)gridDim.y - 1 - blockIdx.y;
    const int m0    = ptile << 6;
    const int kvh   = h >> 3;
    const int tid   = threadIdx.x;
    const int wid   = tid >> 5;
    const int rs    = wid >> 1;
    const int ch    = wid & 1;
    const float scale = 0.08838834764831845f;

    auto load_kv = [&](int kb, int buf) {
        const int k0g = kb << 6;
        const uint32_t base = smem_u32(smc) + OFF_KV + buf * KVBUF;
#pragma unroll
        for (int i = 0; i < 4; i++) {
            int idx = tid + (i << 8);
            int r = idx >> 4, c = idx & 15;
            size_t so = (size_t)(k0g + r) * NKVD + kvh * HD + (c << 3);
            uint32_t off = r * (QLD * 2) + (c << 4);
            cpa16(base + off,         kh + so);
            cpa16(base + 17408 + off, vv + so);
        }
        CPA_COMMIT();
    };

    {
        uint32_t dqh = smem_u32(sQh);
#pragma unroll
        for (int i = 0; i < 4; i++) {
            int idx = tid + (i << 8);
            int r = idx >> 4, c = idx & 15;
            size_t so = (size_t)(m0 + r) * NQ + h * HD + (c << 3);
            uint32_t off = r * (QLD * 2) + (c << 4);
            cpa16(dqh + off, qh + so);
        }
        CPA_COMMIT();
    }
    load_kv(0, 0);

    for (int i = tid; i < 64 * 128 / 4; i += 256)
        ((float4*)sO)[i] = make_float4(0.f, 0.f, 0.f, 0.f);
    if (tid < 64) { sM[tid] = -1e30f; sL[tid] = 0.f; }

    for (int kb = 0; kb <= ptile; kb++) {
        const int k0g = kb << 6;
        const int buf = kb & 1;
        __half* sKh = (__half*)(smc + OFF_KV + buf * KVBUF);
        __half* sV  = (__half*)(smc + OFF_KV + buf * KVBUF + 17408);

        if (kb < ptile) { load_kv(kb + 1, buf ^ 1); CPA_WAIT1(); }
        else            { CPA_WAIT0(); }
        __syncthreads();

        // --- QK^T (single fp16 term) ---
        {
            wmma::fragment<wmma::accumulator, 16, 16, 16, float> accS[2];
            wmma::fill_fragment(accS[0], 0.0f);
            wmma::fill_fragment(accS[1], 0.0f);
#pragma unroll
            for (int k0 = 0; k0 < 128; k0 += 16) {
                wmma::fragment<wmma::matrix_a, 16, 16, 16, __half, wmma::row_major> ah;
                wmma::load_matrix_sync(ah, sQh + rs * 16 * QLD + k0, QLD);
#pragma unroll
                for (int j = 0; j < 2; j++) {
                    wmma::fragment<wmma::matrix_b, 16, 16, 16, __half, wmma::col_major> bh;
                    int kcol = ch * 32 + j * 16;
                    wmma::load_matrix_sync(bh, sKh + kcol * QLD + k0, QLD);
                    wmma::mma_sync(accS[j], ah, bh, accS[j]);
                }
            }
#pragma unroll
            for (int j = 0; j < 2; j++)
                wmma::store_matrix_sync(sS + rs * 16 * SLD + ch * 32 + j * 16,
                                        accS[j], SLD, wmma::mem_row_major);
        }
        __syncthreads();

        // --- online softmax ---
        {
            const int r  = tid >> 2;
            const int q4 = tid & 3;
            float* srow = sS + r * SLD + q4 * 16;
            const int qglob = m0 + r;
            const int kbase = k0g + q4 * 16;

            float vals[16];
            float mx = -1e30f;
#pragma unroll
            for (int j = 0; j < 16; j++) {
                float s = srow[j];
                s = (kbase + j <= qglob) ? s * scale : -1e30f;
                vals[j] = s;
                mx = fmaxf(mx, s);
            }
            mx = fmaxf(mx, __shfl_xor_sync(0xffffffffu, mx, 1));
            mx = fmaxf(mx, __shfl_xor_sync(0xffffffffu, mx, 2));

            float mold = sM[r];
            float mnew = fmaxf(mold, mx);
            float alpha = fexp(mold - mnew);

            __half* prow = sP + r * PLD + q4 * 16;
            float lsum = 0.f;
#pragma unroll
            for (int j = 0; j < 16; j++) {
                float p = fexp(vals[j] - mnew);
                prow[j] = __float2half(p);
                lsum += p;
            }
            lsum += __shfl_xor_sync(0xffffffffu, lsum, 1);
            lsum += __shfl_xor_sync(0xffffffffu, lsum, 2);

            if (q4 == 0) {
                sM[r] = mnew;
                sL[r] = sL[r] * alpha + lsum;
                sA[r] = alpha;
            }
        }
        __syncthreads();

        // --- P @ V ---
        {
            wmma::fragment<wmma::accumulator, 16, 16, 16, float> accO[4];
#pragma unroll
            for (int j = 0; j < 4; j++) wmma::fill_fragment(accO[j], 0.0f);
#pragma unroll
            for (int k0 = 0; k0 < 64; k0 += 16) {
                wmma::fragment<wmma::matrix_a, 16, 16, 16, __half, wmma::row_major> a;
                wmma::load_matrix_sync(a, sP + rs * 16 * PLD + k0, PLD);
#pragma unroll
                for (int j = 0; j < 4; j++) {
                    wmma::fragment<wmma::matrix_b, 16, 16, 16, __half, wmma::row_major> b;
                    wmma::load_matrix_sync(b, sV + k0 * QLD + ch * 64 + j * 16, QLD);
                    wmma::mma_sync(accO[j], a, b, accO[j]);
                }
            }
#pragma unroll
            for (int j = 0; j < 4; j++)
                wmma::store_matrix_sync(sS + rs * 16 * SLD + ch * 64 + j * 16,
                                        accO[j], SLD, wmma::mem_row_major);
        }
        __syncthreads();

        // --- O = O*alpha + PV ---
        {
            const int r  = tid >> 2;
            const int c0 = (tid & 3) << 5;
            const float a = sA[r];
            float4* op = (float4*)(sO + r * 128 + c0);
            const float4* pv = (const float4*)(sS + r * SLD + c0);
#pragma unroll
            for (int j = 0; j < 8; j++) {
                float4 o = op[j], p = pv[j];
                o.x = o.x * a + p.x;
                o.y = o.y * a + p.y;
                o.z = o.z * a + p.z;
                o.w = o.w * a + p.w;
                op[j] = o;
            }
        }
        __syncthreads();
    }

    // Epilogue: normalize, write fp16
    {
        const int r  = tid >> 2;
        const int c0 = (tid & 3) << 5;
        const float inv = 1.0f / sL[r];
        __half* base = attn + (size_t)(m0 + r) * NQ + h * HD + c0;
#pragma unroll
        for (int j = 0; j < 32; j++)
            base[j] = __float2half(sO[r * 128 + c0 + j] * inv);
    }
}

// ---------------------------------------------------------------------------
extern "C" void kernel_launch(void* const* d_in, const int* in_sizes, int n_in,
                              void* d_out, int out_size)
{
    (void)in_sizes; (void)n_in; (void)out_size;
    const float* x  = (const float*)d_in[0];
    const float* wq = (const float*)d_in[1];
    const float* wk = (const float*)d_in[2];
    const float* wv = (const float*)d_in[3];
    const float* wo = (const float*)d_in[4];
    const float* qn = (const float*)d_in[5];
    const float* kn = (const float*)d_in[6];
    const float* cs = (const float*)d_in[7];
    const float* sn = (const float*)d_in[8];
    float* out = (float*)d_out;

    float* qkv;
    cudaGetSymbolAddress((void**)&qkv, g_qkv);

    __half *x16, *wT, *woT, *at16;
    cudaGetSymbolAddress((void**)&x16,  g_x16);
    cudaGetSymbolAddress((void**)&wT,   g_wqkvT);
    cudaGetSymbolAddress((void**)&woT,  g_woT);
    cudaGetSymbolAddress((void**)&at16, g_at16);

    __half *q16h, *k16h, *v16;
    cudaGetSymbolAddress((void**)&q16h, g_q16h);
    cudaGetSymbolAddress((void**)&k16h, g_k16h);
    cudaGetSymbolAddress((void**)&v16,  g_v16);

    cudaFuncSetAttribute(gemm_mma_f16,
                         cudaFuncAttributeMaxDynamicSharedMemorySize, GEMM_SMEM);
    cudaFuncSetAttribute(flash_wmma,
                         cudaFuncAttributeMaxDynamicSharedMemorySize, FLASH_SMEM);

    // Convert activations to fp16; transpose weights to fp16 [N][K]
    cvt_f16v<<<(S_LEN * HID / 4 + 255) / 256, 256>>>(
        (const float4*)x, (uint2*)x16, S_LEN * HID / 4);
    transpose_f16<<<dim3(NQ / 32,   HID / 32), dim3(32, 8)>>>(wq, wT, HID, NQ);
    transpose_f16<<<dim3(NKVD / 32, HID / 32), dim3(32, 8)>>>(
        wk, wT + (size_t)NQ * HID, HID, NKVD);
    transpose_f16<<<dim3(NKVD / 32, HID / 32), dim3(32, 8)>>>(
        wv, wT + (size_t)(NQ + NKVD) * HID, HID, NKVD);
    transpose_f16<<<dim3(HID / 32,  NQ / 32),  dim3(32, 8)>>>(wo, woT, NQ, HID);

    // Fused QKV projection (single fp16 HMMA)
    gemm_mma_f16<<<dim3(NQKV / 128, S_LEN / 128), 256, GEMM_SMEM>>>(
        x16, wT, qkv, NQKV, HID);

    // RMSNorm + RoPE -> fp16; V -> fp16
    rmsnorm_rope_f16<<<S_LEN * NH,  128>>>(qkv, 0,  qn, cs, sn, NH,  q16h);
    rmsnorm_rope_f16<<<S_LEN * NKV, 128>>>(qkv, NQ, kn, cs, sn, NKV, k16h);
    cvt_v16<<<(S_LEN * NKVD) / 256, 256>>>(qkv, v16);

    // Flash attention -> fp16
    flash_wmma<<<dim3(NH, S_LEN / 64), 256, FLASH_SMEM>>>(
        q16h, k16h, v16, at16);

    // Output projection (single fp16 HMMA)
    gemm_mma_f16<<<dim3(HID / 128, S_LEN / 128), 256, GEMM_SMEM>>>(
        at16, woT, out, HID, NQ);
}

// round 14
// speedup vs baseline: 1.2485x; 1.0900x over previous
#include <cuda_runtime.h>
#include <cuda_bf16.h>
#include <cuda_fp16.h>
#include <cstdint>
#include <math.h>

#define S_LEN 2048
#define HID   2048
#define NH    32
#define NKV   4
#define HD    128
#define NQ    (NH * HD)    // 4096
#define NKVD  (NKV * HD)   // 512
#define NQKV  (NQ + 2 * NKVD)  // 5120

// ---------------------------------------------------------------------------
// Scratch (device globals — no allocation allowed)
// ---------------------------------------------------------------------------
__device__ float g_qkv[S_LEN * NQKV];

__device__ __half g_x16[S_LEN * HID];
__device__ __half g_w16q[HID * NQ];      // fp16 weights, original [K][N] layout
__device__ __half g_w16k[HID * NKVD];
__device__ __half g_w16v[HID * NKVD];
__device__ __half g_wo16[NQ * HID];
__device__ __half g_at16[S_LEN * NQ];

__device__ __half g_q16h[S_LEN * NQ];
__device__ __half g_k16h[S_LEN * NKVD];
__device__ __half g_v16[S_LEN * NKVD];

// ---------------------------------------------------------------------------
// helpers
// ---------------------------------------------------------------------------
__device__ __forceinline__ uint32_t smem_u32(const void* p) {
    uint32_t a;
    asm("{ .reg .u64 t; cvta.to.shared.u64 t, %1; cvt.u32.u64 %0, t; }"
        : "=r"(a) : "l"(p));
    return a;
}

__device__ __forceinline__ void cpa16(uint32_t dst, const void* src) {
    asm volatile(
        "{\n\t.reg .u64 g;\n\tcvta.to.global.u64 g, %1;\n\t"
        "cp.async.cg.shared.global [%0], [g], 16;\n\t}"
        :: "r"(dst), "l"(src) : "memory");
}
#define CPA_COMMIT() asm volatile("cp.async.commit_group;" ::: "memory")
#define CPA_WAIT1()  asm volatile("cp.async.wait_group 1;" ::: "memory")
#define CPA_WAIT0()  asm volatile("cp.async.wait_group 0;" ::: "memory")

#define LDSM4(r, addr) \
    asm volatile("ldmatrix.sync.aligned.m8n8.x4.shared.b16 {%0,%1,%2,%3}, [%4];" \
        : "=r"((r)[0]), "=r"((r)[1]), "=r"((r)[2]), "=r"((r)[3]) : "r"(addr))

// Transposed ldmatrix: loads B fragments directly from row-major [K][N] tiles.
#define LDSM4T(r, addr) \
    asm volatile("ldmatrix.sync.aligned.m8n8.x4.trans.shared.b16 {%0,%1,%2,%3}, [%4];" \
        : "=r"((r)[0]), "=r"((r)[1]), "=r"((r)[2]), "=r"((r)[3]) : "r"(addr))

__device__ __forceinline__ void mma16816f(float* d, const uint32_t* a,
                                          uint32_t b0, uint32_t b1) {
    asm volatile(
        "mma.sync.aligned.m16n8k16.row.col.f32.f16.f16.f32 "
        "{%0,%1,%2,%3}, {%4,%5,%6,%7}, {%8,%9}, {%0,%1,%2,%3};"
        : "+f"(d[0]), "+f"(d[1]), "+f"(d[2]), "+f"(d[3])
        : "r"(a[0]), "r"(a[1]), "r"(a[2]), "r"(a[3]), "r"(b0), "r"(b1));
}

// Fast exp on the FFMA pipe. Rel err < 3e-6 on [-87, 0].
__device__ __forceinline__ float fexp(float x) {
    x = fmaxf(x, -87.0f);
    float z  = fmaf(x, 1.44269504089f, 12582912.0f);
    float nf = z - 12582912.0f;
    float f  = fmaf(x, 1.44269504089f, -nf);
    float p  = 1.333355815e-3f;
    p = fmaf(p, f, 9.618129107e-3f);
    p = fmaf(p, f, 5.550410866e-2f);
    p = fmaf(p, f, 2.402265069e-1f);
    p = fmaf(p, f, 6.931471806e-1f);
    p = fmaf(p, f, 1.0f);
    int n = __float_as_int(z) - 0x4B400000;
    return __int_as_float(__float_as_int(p) + (n << 23));
}

// ---------------------------------------------------------------------------
// aux kernels
// ---------------------------------------------------------------------------
__global__ void cvt_f16v(const float4* __restrict__ in,
                         uint2* __restrict__ o, int n4)
{
    int i = blockIdx.x * blockDim.x + threadIdx.x;
    if (i < n4) {
        float4 v = in[i];
        __half2 a = __halves2half2(__float2half(v.x), __float2half(v.y));
        __half2 b = __halves2half2(__float2half(v.z), __float2half(v.w));
        uint2 r;
        r.x = *(uint32_t*)&a; r.y = *(uint32_t*)&b;
        o[i] = r;
    }
}

__global__ void cvt_v16(const float* __restrict__ qkv, __half* __restrict__ out)
{
    int i = blockIdx.x * blockDim.x + threadIdx.x;
    int s = i >> 9, d = i & 511;
    out[i] = __float2half(qkv[(size_t)s * NQKV + NQ + NKVD + d]);
}

// ---------------------------------------------------------------------------
// Raw-HMMA fp16 GEMM with row-major [K][N] B (no weight transpose needed):
// C[m][n] = sum_k A[m][k] * B[k][n]
// CTA 128x128, 8 warps (2x4), warp tile 64x32. K chunks of 32, 3-stage
// cp.async, one __syncthreads per chunk. A rows 80 B, B rows 272 B
// (conflict-free for both ldmatrix variants).
// B resolved per N-tile from {B0 (cols<nq), B1, B2} for the fused QKV launch.
// ---------------------------------------------------------------------------
#define RPAD_A 80
#define ATILE  (128 * RPAD_A)            // 10240
#define BLDB   272
#define BTILE  (32 * BLDB)               // 8704
#define STG_T  (ATILE + BTILE)           // 18944
#define GEMM_SMEM (3 * STG_T)            // 56832 (2 CTAs/SM)

__global__ void __launch_bounds__(256, 2) gemm_mma_f16t(
    const __half* __restrict__ A,
    const __half* __restrict__ B0, const __half* __restrict__ B1,
    const __half* __restrict__ B2,
    int nq, int nkv, int ld0, int ldkv,
    float* __restrict__ C, int N, int K)
{
    extern __shared__ char smraw[];
    const int tid  = threadIdx.x;
    const int wid  = tid >> 5, lane = tid & 31;
    const int m0 = blockIdx.y << 7, n0 = blockIdx.x << 7;
    const int wm = wid >> 2;             // 0..1  (64-row slab)
    const int wn = wid & 3;              // 0..3  (32-col slab)

    const uint32_t sbase = smem_u32(smraw);

    // Resolve which weight matrix this N-tile lives in
    const __half* Bp; int ldB, nloc;
    if (n0 < nq)            { Bp = B0; ldB = ld0;  nloc = n0; }
    else if (n0 < nq + nkv) { Bp = B1; ldB = ldkv; nloc = n0 - nq; }
    else                    { Bp = B2; ldB = ldkv; nloc = n0 - nq - nkv; }

    float acc[4][4][4];
#pragma unroll
    for (int i = 0; i < 4; i++)
#pragma unroll
        for (int j = 0; j < 4; j++)
#pragma unroll
            for (int r = 0; r < 4; r++) acc[i][j][r] = 0.0f;

    const uint32_t lrow = lane & 15;
    const uint32_t lkof = (lane >> 4) << 4;
    const int nck = K >> 5;

    auto load_stage = [&](int ck, int st) {
        const int k0 = ck << 5;
        const uint32_t sb = sbase + st * STG_T;
        // A tile: 128 m-rows x 32 k fp16 (64 B data / 80 B row)
#pragma unroll
        for (int i = 0; i < 2; i++) {
            int idx = (i << 8) + tid;          // 0..511
            int row = idx >> 2, c = idx & 3;
            cpa16(sb + row * RPAD_A + c * 16,
                  A + (size_t)(m0 + row) * K + k0 + c * 8);
        }
        // B tile: 32 k-rows x 128 n fp16 (256 B data / 272 B row)
#pragma unroll
        for (int i = 0; i < 2; i++) {
            int idx = (i << 8) + tid;          // 0..511
            int row = idx >> 4, c = idx & 15;
            cpa16(sb + ATILE + row * BLDB + c * 16,
                  Bp + (size_t)(k0 + row) * ldB + nloc + c * 8);
        }
        CPA_COMMIT();
    };

    load_stage(0, 0);
    load_stage(1, 1);

    int s = 0;
    for (int ck = 0; ck < nck; ck++) {
        if (ck + 1 < nck) { CPA_WAIT1(); } else { CPA_WAIT0(); }
        __syncthreads();
        if (ck + 2 < nck) {
            int s2 = s + 2; if (s2 >= 3) s2 -= 3;
            load_stage(ck + 2, s2);
        }

        const uint32_t sb = sbase + s * STG_T;
        const uint32_t ab = sb + (wm * 64 + lrow) * RPAD_A + lkof;
        // B trans-ldmatrix lane address: row = k-sub + (lane&15),
        // col = warp n-base + 8*(lane>>4)
        const uint32_t bb = sb + ATILE + (lane & 15) * BLDB
                          + (wn * 32 + ((lane >> 4) << 3)) * 2;

#pragma unroll
        for (int kk = 0; kk < 2; kk++) {
            const uint32_t koA = kk * 32;          // bytes into A k-dim
            const uint32_t koB = kk * 16 * BLDB;   // 16 k-rows into B tile
            uint32_t bt[2][4];
            LDSM4T(bt[0], bb + koB);               // n cols [0,16)  of warp slab
            LDSM4T(bt[1], bb + koB + 32);          // n cols [16,32)
#pragma unroll
            for (int mt = 0; mt < 4; mt++) {
                uint32_t ah[4];
                LDSM4(ah, ab + mt * 16 * RPAD_A + koA);
#pragma unroll
                for (int nt = 0; nt < 4; nt++) {
                    const int j = nt >> 1, g = nt & 1;
                    // bt[j]: r0=(k0-7,n-lo) r1=(k8-15,n-lo) r2=(k0-7,n-hi) r3=(k8-15,n-hi)
                    mma16816f(acc[mt][nt], ah, bt[j][g * 2], bt[j][g * 2 + 1]);
                }
            }
        }
        if (++s >= 3) s -= 3;
    }

    const int erow = (lane >> 2);
    const int ecol = (lane & 3) << 1;
#pragma unroll
    for (int mt = 0; mt < 4; mt++) {
#pragma unroll
        for (int nt = 0; nt < 4; nt++) {
            const int r = m0 + wm * 64 + mt * 16 + erow;
            const int c = n0 + wn * 32 + nt * 8 + ecol;
            *(float2*)(C + (size_t)r * N + c) =
                make_float2(acc[mt][nt][0], acc[mt][nt][1]);
            *(float2*)(C + (size_t)(r + 8) * N + c) =
                make_float2(acc[mt][nt][2], acc[mt][nt][3]);
        }
    }
}

// ---------------------------------------------------------------------------
// Fused RMSNorm + RoPE, reading a column slice of fused qkv -> fp16
// ---------------------------------------------------------------------------
__global__ __launch_bounds__(128) void rmsnorm_rope_f16(
    const float* __restrict__ qkv, int colOff, const float* __restrict__ w,
    const float* __restrict__ cs, const float* __restrict__ sn, int heads,
    __half* __restrict__ oh)
{
    const int b = blockIdx.x;
    const int s = b / heads;
    const int h = b - s * heads;
    const int d = threadIdx.x;

    const size_t io = (size_t)s * NQKV + colOff + h * HD;
    const size_t oo = ((size_t)s * heads + h) * HD;
    float v = qkv[io + d];

    float ssq = v * v;
#pragma unroll
    for (int off = 16; off > 0; off >>= 1)
        ssq += __shfl_xor_sync(0xffffffffu, ssq, off);

    __shared__ float red[4];
    __shared__ float sh[HD];
    if ((d & 31) == 0) red[d >> 5] = ssq;
    __syncthreads();
    float tot = red[0] + red[1] + red[2] + red[3];

    float xn = v * rsqrtf(tot * (1.0f / HD) + 1e-6f) * w[d];
    sh[d] = xn;
    __syncthreads();

    float partner = (d < 64) ? -sh[d + 64] : sh[d - 64];
    float res = xn * cs[s * HD + d] + partner * sn[s * HD + d];

    oh[oo + d] = __float2half(res);
}

// ---------------------------------------------------------------------------
// Tensor-core flash attention, double-buffered K/V prefetch (R13 proven).
// ---------------------------------------------------------------------------
#include <mma.h>
using namespace nvcuda;

#define QLD 136
#define SLD 132
#define PLD 72

#define OFF_QH 0
#define OFF_KV 17408          // per-buf: KH +0, V +17408
#define KVBUF  34816
#define OFF_S  87040
#define OFF_P  120832
#define OFF_O  130048
#define OFF_M  162816
#define OFF_L  163072
#define OFF_AL 163328
#define FLASH_SMEM 163584

__global__ void __launch_bounds__(256) flash_wmma(
    const __half* __restrict__ qh,
    const __half* __restrict__ kh, const __half* __restrict__ vv,
    __half* __restrict__ attn)
{
    extern __shared__ char smc[];
    __half* sQh = (__half*)(smc + OFF_QH);
    float*  sS  = (float*)(smc + OFF_S);
    __half* sP  = (__half*)(smc + OFF_P);
    float*  sO  = (float*)(smc + OFF_O);
    float*  sM  = (float*)(smc + OFF_M);
    float*  sL  = (float*)(smc + OFF_L);
    float*  sA  = (float*)(smc + OFF_AL);

    const int h     = blockIdx.x;
    const int ptile = (int)gridDim.y - 1 - blockIdx.y;
    const int m0    = ptile << 6;
    const int kvh   = h >> 3;
    const int tid   = threadIdx.x;
    const int wid   = tid >> 5;
    const int rs    = wid >> 1;
    const int ch    = wid & 1;
    const float scale = 0.08838834764831845f;

    auto load_kv = [&](int kb, int buf) {
        const int k0g = kb << 6;
        const uint32_t base = smem_u32(smc) + OFF_KV + buf * KVBUF;
#pragma unroll
        for (int i = 0; i < 4; i++) {
            int idx = tid + (i << 8);
            int r = idx >> 4, c = idx & 15;
            size_t so = (size_t)(k0g + r) * NKVD + kvh * HD + (c << 3);
            uint32_t off = r * (QLD * 2) + (c << 4);
            cpa16(base + off,         kh + so);
            cpa16(base + 17408 + off, vv + so);
        }
        CPA_COMMIT();
    };

    {
        uint32_t dqh = smem_u32(sQh);
#pragma unroll
        for (int i = 0; i < 4; i++) {
            int idx = tid + (i << 8);
            int r = idx >> 4, c = idx & 15;
            size_t so = (size_t)(m0 + r) * NQ + h * HD + (c << 3);
            uint32_t off = r * (QLD * 2) + (c << 4);
            cpa16(dqh + off, qh + so);
        }
        CPA_COMMIT();
    }
    load_kv(0, 0);

    for (int i = tid; i < 64 * 128 / 4; i += 256)
        ((float4*)sO)[i] = make_float4(0.f, 0.f, 0.f, 0.f);
    if (tid < 64) { sM[tid] = -1e30f; sL[tid] = 0.f; }

    for (int kb = 0; kb <= ptile; kb++) {
        const int k0g = kb << 6;
        const int buf = kb & 1;
        __half* sKh = (__half*)(smc + OFF_KV + buf * KVBUF);
        __half* sV  = (__half*)(smc + OFF_KV + buf * KVBUF + 17408);

        if (kb < ptile) { load_kv(kb + 1, buf ^ 1); CPA_WAIT1(); }
        else            { CPA_WAIT0(); }
        __syncthreads();

        // --- QK^T ---
        {
            wmma::fragment<wmma::accumulator, 16, 16, 16, float> accS[2];
            wmma::fill_fragment(accS[0], 0.0f);
            wmma::fill_fragment(accS[1], 0.0f);
#pragma unroll
            for (int k0 = 0; k0 < 128; k0 += 16) {
                wmma::fragment<wmma::matrix_a, 16, 16, 16, __half, wmma::row_major> ah;
                wmma::load_matrix_sync(ah, sQh + rs * 16 * QLD + k0, QLD);
#pragma unroll
                for (int j = 0; j < 2; j++) {
                    wmma::fragment<wmma::matrix_b, 16, 16, 16, __half, wmma::col_major> bh;
                    int kcol = ch * 32 + j * 16;
                    wmma::load_matrix_sync(bh, sKh + kcol * QLD + k0, QLD);
                    wmma::mma_sync(accS[j], ah, bh, accS[j]);
                }
            }
#pragma unroll
            for (int j = 0; j < 2; j++)
                wmma::store_matrix_sync(sS + rs * 16 * SLD + ch * 32 + j * 16,
                                        accS[j], SLD, wmma::mem_row_major);
        }
        __syncthreads();

        // --- online softmax ---
        {
            const int r  = tid >> 2;
            const int q4 = tid & 3;
            float* srow = sS + r * SLD + q4 * 16;
            const int qglob = m0 + r;
            const int kbase = k0g + q4 * 16;

            float vals[16];
            float mx = -1e30f;
#pragma unroll
            for (int j = 0; j < 16; j++) {
                float s = srow[j];
                s = (kbase + j <= qglob) ? s * scale : -1e30f;
                vals[j] = s;
                mx = fmaxf(mx, s);
            }
            mx = fmaxf(mx, __shfl_xor_sync(0xffffffffu, mx, 1));
            mx = fmaxf(mx, __shfl_xor_sync(0xffffffffu, mx, 2));

            float mold = sM[r];
            float mnew = fmaxf(mold, mx);
            float alpha = fexp(mold - mnew);

            __half* prow = sP + r * PLD + q4 * 16;
            float lsum = 0.f;
#pragma unroll
            for (int j = 0; j < 16; j++) {
                float p = fexp(vals[j] - mnew);
                prow[j] = __float2half(p);
                lsum += p;
            }
            lsum += __shfl_xor_sync(0xffffffffu, lsum, 1);
            lsum += __shfl_xor_sync(0xffffffffu, lsum, 2);

            if (q4 == 0) {
                sM[r] = mnew;
                sL[r] = sL[r] * alpha + lsum;
                sA[r] = alpha;
            }
        }
        __syncthreads();

        // --- P @ V ---
        {
            wmma::fragment<wmma::accumulator, 16, 16, 16, float> accO[4];
#pragma unroll
            for (int j = 0; j < 4; j++) wmma::fill_fragment(accO[j], 0.0f);
#pragma unroll
            for (int k0 = 0; k0 < 64; k0 += 16) {
                wmma::fragment<wmma::matrix_a, 16, 16, 16, __half, wmma::row_major> a;
                wmma::load_matrix_sync(a, sP + rs * 16 * PLD + k0, PLD);
#pragma unroll
                for (int j = 0; j < 4; j++) {
                    wmma::fragment<wmma::matrix_b, 16, 16, 16, __half, wmma::row_major> b;
                    wmma::load_matrix_sync(b, sV + k0 * QLD + ch * 64 + j * 16, QLD);
                    wmma::mma_sync(accO[j], a, b, accO[j]);
                }
            }
#pragma unroll
            for (int j = 0; j < 4; j++)
                wmma::store_matrix_sync(sS + rs * 16 * SLD + ch * 64 + j * 16,
                                        accO[j], SLD, wmma::mem_row_major);
        }
        __syncthreads();

        // --- O = O*alpha + PV ---
        {
            const int r  = tid >> 2;
            const int c0 = (tid & 3) << 5;
            const float a = sA[r];
            float4* op = (float4*)(sO + r * 128 + c0);
            const float4* pv = (const float4*)(sS + r * SLD + c0);
#pragma unroll
            for (int j = 0; j < 8; j++) {
                float4 o = op[j], p = pv[j];
                o.x = o.x * a + p.x;
                o.y = o.y * a + p.y;
                o.z = o.z * a + p.z;
                o.w = o.w * a + p.w;
                op[j] = o;
            }
        }
        __syncthreads();
    }

    // Epilogue: normalize, write fp16
    {
        const int r  = tid >> 2;
        const int c0 = (tid & 3) << 5;
        const float inv = 1.0f / sL[r];
        __half* base = attn + (size_t)(m0 + r) * NQ + h * HD + c0;
#pragma unroll
        for (int j = 0; j < 32; j++)
            base[j] = __float2half(sO[r * 128 + c0 + j] * inv);
    }
}

// ---------------------------------------------------------------------------
extern "C" void kernel_launch(void* const* d_in, const int* in_sizes, int n_in,
                              void* d_out, int out_size)
{
    (void)in_sizes; (void)n_in; (void)out_size;
    const float* x  = (const float*)d_in[0];
    const float* wq = (const float*)d_in[1];
    const float* wk = (const float*)d_in[2];
    const float* wv = (const float*)d_in[3];
    const float* wo = (const float*)d_in[4];
    const float* qn = (const float*)d_in[5];
    const float* kn = (const float*)d_in[6];
    const float* cs = (const float*)d_in[7];
    const float* sn = (const float*)d_in[8];
    float* out = (float*)d_out;

    float* qkv;
    cudaGetSymbolAddress((void**)&qkv, g_qkv);

    __half *x16, *w16q, *w16k, *w16v, *wo16, *at16;
    cudaGetSymbolAddress((void**)&x16,  g_x16);
    cudaGetSymbolAddress((void**)&w16q, g_w16q);
    cudaGetSymbolAddress((void**)&w16k, g_w16k);
    cudaGetSymbolAddress((void**)&w16v, g_w16v);
    cudaGetSymbolAddress((void**)&wo16, g_wo16);
    cudaGetSymbolAddress((void**)&at16, g_at16);

    __half *q16h, *k16h, *v16;
    cudaGetSymbolAddress((void**)&q16h, g_q16h);
    cudaGetSymbolAddress((void**)&k16h, g_k16h);
    cudaGetSymbolAddress((void**)&v16,  g_v16);

    cudaFuncSetAttribute(gemm_mma_f16t,
                         cudaFuncAttributeMaxDynamicSharedMemorySize, GEMM_SMEM);
    cudaFuncSetAttribute(flash_wmma,
                         cudaFuncAttributeMaxDynamicSharedMemorySize, FLASH_SMEM);

    // Pure streaming fp32 -> fp16 converts (no transposes)
    cvt_f16v<<<(S_LEN * HID / 4 + 255) / 256, 256>>>(
        (const float4*)x, (uint2*)x16, S_LEN * HID / 4);
    cvt_f16v<<<(HID * NQ / 4 + 255) / 256, 256>>>(
        (const float4*)wq, (uint2*)w16q, HID * NQ / 4);
    cvt_f16v<<<(HID * NKVD / 4 + 255) / 256, 256>>>(
        (const float4*)wk, (uint2*)w16k, HID * NKVD / 4);
    cvt_f16v<<<(HID * NKVD / 4 + 255) / 256, 256>>>(
        (const float4*)wv, (uint2*)w16v, HID * NKVD / 4);
    cvt_f16v<<<(NQ * HID / 4 + 255) / 256, 256>>>(
        (const float4*)wo, (uint2*)wo16, NQ * HID / 4);

    // Fused QKV projection (fp16 HMMA, B row-major via ldmatrix.trans)
    gemm_mma_f16t<<<dim3(NQKV / 128, S_LEN / 128), 256, GEMM_SMEM>>>(
        x16, w16q, w16k, w16v, NQ, NKVD, NQ, NKVD, qkv, NQKV, HID);

    // RMSNorm + RoPE -> fp16; V -> fp16
    rmsnorm_rope_f16<<<S_LEN * NH,  128>>>(qkv, 0,  qn, cs, sn, NH,  q16h);
    rmsnorm_rope_f16<<<S_LEN * NKV, 128>>>(qkv, NQ, kn, cs, sn, NKV, k16h);
    cvt_v16<<<(S_LEN * NKVD) / 256, 256>>>(qkv, v16);

    // Flash attention -> fp16
    flash_wmma<<<dim3(NH, S_LEN / 64), 256, FLASH_SMEM>>>(
        q16h, k16h, v16, at16);

    // Output projection: wo is [NQ][HID] = [K][N], first branch always taken
    gemm_mma_f16t<<<dim3(HID / 128, S_LEN / 128), 256, GEMM_SMEM>>>(
        at16, wo16, wo16, wo16, HID, HID, HID, HID, out, HID, NQ);
}

// round 15
// speedup vs baseline: 2.1873x; 1.7520x over previous
#include <cuda_runtime.h>
#include <cuda_bf16.h>
#include <cuda_fp16.h>
#include <cstdint>
#include <math.h>

#define S_LEN 2048
#define HID   2048
#define NH    32
#define NKV   4
#define HD    128
#define NQ    (NH * HD)    // 4096
#define NKVD  (NKV * HD)   // 512
#define NQKV  (NQ + 2 * NKVD)  // 5120

// ---------------------------------------------------------------------------
// Scratch (device globals — no allocation allowed)
// ---------------------------------------------------------------------------
__device__ float g_qkv[S_LEN * NQKV];

__device__ __half g_x16[S_LEN * HID];
__device__ __half g_w16q[HID * NQ];      // fp16 weights, original [K][N] layout
__device__ __half g_w16k[HID * NKVD];
__device__ __half g_w16v[HID * NKVD];
__device__ __half g_wo16[NQ * HID];
__device__ __half g_at16[S_LEN * NQ];

__device__ __half g_q16h[S_LEN * NQ];
__device__ __half g_k16h[S_LEN * NKVD];
__device__ __half g_v16[S_LEN * NKVD];

// ---------------------------------------------------------------------------
// helpers
// ---------------------------------------------------------------------------
__device__ __forceinline__ uint32_t smem_u32(const void* p) {
    uint32_t a;
    asm("{ .reg .u64 t; cvta.to.shared.u64 t, %1; cvt.u32.u64 %0, t; }"
        : "=r"(a) : "l"(p));
    return a;
}

__device__ __forceinline__ void cpa16(uint32_t dst, const void* src) {
    asm volatile(
        "{\n\t.reg .u64 g;\n\tcvta.to.global.u64 g, %1;\n\t"
        "cp.async.cg.shared.global [%0], [g], 16;\n\t}"
        :: "r"(dst), "l"(src) : "memory");
}
#define CPA_COMMIT() asm volatile("cp.async.commit_group;" ::: "memory")
#define CPA_WAIT1()  asm volatile("cp.async.wait_group 1;" ::: "memory")
#define CPA_WAIT0()  asm volatile("cp.async.wait_group 0;" ::: "memory")

#define LDSM4(r, addr) \
    asm volatile("ldmatrix.sync.aligned.m8n8.x4.shared.b16 {%0,%1,%2,%3}, [%4];" \
        : "=r"((r)[0]), "=r"((r)[1]), "=r"((r)[2]), "=r"((r)[3]) : "r"(addr))

#define LDSM4T(r, addr) \
    asm volatile("ldmatrix.sync.aligned.m8n8.x4.trans.shared.b16 {%0,%1,%2,%3}, [%4];" \
        : "=r"((r)[0]), "=r"((r)[1]), "=r"((r)[2]), "=r"((r)[3]) : "r"(addr))

__device__ __forceinline__ void mma16816f(float* d, const uint32_t* a,
                                          uint32_t b0, uint32_t b1) {
    asm volatile(
        "mma.sync.aligned.m16n8k16.row.col.f32.f16.f16.f32 "
        "{%0,%1,%2,%3}, {%4,%5,%6,%7}, {%8,%9}, {%0,%1,%2,%3};"
        : "+f"(d[0]), "+f"(d[1]), "+f"(d[2]), "+f"(d[3])
        : "r"(a[0]), "r"(a[1]), "r"(a[2]), "r"(a[3]), "r"(b0), "r"(b1));
}

// Fast exp on the FFMA pipe. Rel err < 3e-6 on [-87, 0].
__device__ __forceinline__ float fexp(float x) {
    x = fmaxf(x, -87.0f);
    float z  = fmaf(x, 1.44269504089f, 12582912.0f);
    float nf = z - 12582912.0f;
    float f  = fmaf(x, 1.44269504089f, -nf);
    float p  = 1.333355815e-3f;
    p = fmaf(p, f, 9.618129107e-3f);
    p = fmaf(p, f, 5.550410866e-2f);
    p = fmaf(p, f, 2.402265069e-1f);
    p = fmaf(p, f, 6.931471806e-1f);
    p = fmaf(p, f, 1.0f);
    int n = __float_as_int(z) - 0x4B400000;
    return __int_as_float(__float_as_int(p) + (n << 23));
}

// ---------------------------------------------------------------------------
// aux kernels
// ---------------------------------------------------------------------------
__global__ void cvt_f16v(const float4* __restrict__ in,
                         uint2* __restrict__ o, int n4)
{
    int i = blockIdx.x * blockDim.x + threadIdx.x;
    if (i < n4) {
        float4 v = in[i];
        __half2 a = __halves2half2(__float2half(v.x), __float2half(v.y));
        __half2 b = __halves2half2(__float2half(v.z), __float2half(v.w));
        uint2 r;
        r.x = *(uint32_t*)&a; r.y = *(uint32_t*)&b;
        o[i] = r;
    }
}

__global__ void cvt_v16(const float* __restrict__ qkv, __half* __restrict__ out)
{
    int i = blockIdx.x * blockDim.x + threadIdx.x;
    int s = i >> 9, d = i & 511;
    out[i] = __float2half(qkv[(size_t)s * NQKV + NQ + NKVD + d]);
}

// ---------------------------------------------------------------------------
// Raw-HMMA fp16 GEMM with row-major [K][N] B (R14 proven, unchanged)
// ---------------------------------------------------------------------------
#define RPAD_A 80
#define ATILE  (128 * RPAD_A)            // 10240
#define BLDB   272
#define BTILE  (32 * BLDB)               // 8704
#define STG_T  (ATILE + BTILE)           // 18944
#define GEMM_SMEM (3 * STG_T)            // 56832 (2 CTAs/SM)

__global__ void __launch_bounds__(256, 2) gemm_mma_f16t(
    const __half* __restrict__ A,
    const __half* __restrict__ B0, const __half* __restrict__ B1,
    const __half* __restrict__ B2,
    int nq, int nkv, int ld0, int ldkv,
    float* __restrict__ C, int N, int K)
{
    extern __shared__ char smraw[];
    const int tid  = threadIdx.x;
    const int wid  = tid >> 5, lane = tid & 31;
    const int m0 = blockIdx.y << 7, n0 = blockIdx.x << 7;
    const int wm = wid >> 2;
    const int wn = wid & 3;

    const uint32_t sbase = smem_u32(smraw);

    const __half* Bp; int ldB, nloc;
    if (n0 < nq)            { Bp = B0; ldB = ld0;  nloc = n0; }
    else if (n0 < nq + nkv) { Bp = B1; ldB = ldkv; nloc = n0 - nq; }
    else                    { Bp = B2; ldB = ldkv; nloc = n0 - nq - nkv; }

    float acc[4][4][4];
#pragma unroll
    for (int i = 0; i < 4; i++)
#pragma unroll
        for (int j = 0; j < 4; j++)
#pragma unroll
            for (int r = 0; r < 4; r++) acc[i][j][r] = 0.0f;

    const uint32_t lrow = lane & 15;
    const uint32_t lkof = (lane >> 4) << 4;
    const int nck = K >> 5;

    auto load_stage = [&](int ck, int st) {
        const int k0 = ck << 5;
        const uint32_t sb = sbase + st * STG_T;
#pragma unroll
        for (int i = 0; i < 2; i++) {
            int idx = (i << 8) + tid;
            int row = idx >> 2, c = idx & 3;
            cpa16(sb + row * RPAD_A + c * 16,
                  A + (size_t)(m0 + row) * K + k0 + c * 8);
        }
#pragma unroll
        for (int i = 0; i < 2; i++) {
            int idx = (i << 8) + tid;
            int row = idx >> 4, c = idx & 15;
            cpa16(sb + ATILE + row * BLDB + c * 16,
                  Bp + (size_t)(k0 + row) * ldB + nloc + c * 8);
        }
        CPA_COMMIT();
    };

    load_stage(0, 0);
    load_stage(1, 1);

    int s = 0;
    for (int ck = 0; ck < nck; ck++) {
        if (ck + 1 < nck) { CPA_WAIT1(); } else { CPA_WAIT0(); }
        __syncthreads();
        if (ck + 2 < nck) {
            int s2 = s + 2; if (s2 >= 3) s2 -= 3;
            load_stage(ck + 2, s2);
        }

        const uint32_t sb = sbase + s * STG_T;
        const uint32_t ab = sb + (wm * 64 + lrow) * RPAD_A + lkof;
        const uint32_t bb = sb + ATILE + (lane & 15) * BLDB
                          + (wn * 32 + ((lane >> 4) << 3)) * 2;

#pragma unroll
        for (int kk = 0; kk < 2; kk++) {
            const uint32_t koA = kk * 32;
            const uint32_t koB = kk * 16 * BLDB;
            uint32_t bt[2][4];
            LDSM4T(bt[0], bb + koB);
            LDSM4T(bt[1], bb + koB + 32);
#pragma unroll
            for (int mt = 0; mt < 4; mt++) {
                uint32_t ah[4];
                LDSM4(ah, ab + mt * 16 * RPAD_A + koA);
#pragma unroll
                for (int nt = 0; nt < 4; nt++) {
                    const int j = nt >> 1, g = nt & 1;
                    mma16816f(acc[mt][nt], ah, bt[j][g * 2], bt[j][g * 2 + 1]);
                }
            }
        }
        if (++s >= 3) s -= 3;
    }

    const int erow = (lane >> 2);
    const int ecol = (lane & 3) << 1;
#pragma unroll
    for (int mt = 0; mt < 4; mt++) {
#pragma unroll
        for (int nt = 0; nt < 4; nt++) {
            const int r = m0 + wm * 64 + mt * 16 + erow;
            const int c = n0 + wn * 32 + nt * 8 + ecol;
            *(float2*)(C + (size_t)r * N + c) =
                make_float2(acc[mt][nt][0], acc[mt][nt][1]);
            *(float2*)(C + (size_t)(r + 8) * N + c) =
                make_float2(acc[mt][nt][2], acc[mt][nt][3]);
        }
    }
}

// ---------------------------------------------------------------------------
// Fused RMSNorm + RoPE (unchanged)
// ---------------------------------------------------------------------------
__global__ __launch_bounds__(128) void rmsnorm_rope_f16(
    const float* __restrict__ qkv, int colOff, const float* __restrict__ w,
    const float* __restrict__ cs, const float* __restrict__ sn, int heads,
    __half* __restrict__ oh)
{
    const int b = blockIdx.x;
    const int s = b / heads;
    const int h = b - s * heads;
    const int d = threadIdx.x;

    const size_t io = (size_t)s * NQKV + colOff + h * HD;
    const size_t oo = ((size_t)s * heads + h) * HD;
    float v = qkv[io + d];

    float ssq = v * v;
#pragma unroll
    for (int off = 16; off > 0; off >>= 1)
        ssq += __shfl_xor_sync(0xffffffffu, ssq, off);

    __shared__ float red[4];
    __shared__ float sh[HD];
    if ((d & 31) == 0) red[d >> 5] = ssq;
    __syncthreads();
    float tot = red[0] + red[1] + red[2] + red[3];

    float xn = v * rsqrtf(tot * (1.0f / HD) + 1e-6f) * w[d];
    sh[d] = xn;
    __syncthreads();

    float partner = (d < 64) ? -sh[d + 64] : sh[d - 64];
    float res = xn * cs[s * HD + d] + partner * sn[s * HD + d];

    oh[oo + d] = __float2half(res);
}

// ---------------------------------------------------------------------------
// Flash attention v2: O in registers (raw PV mma), 80 KB smem -> 2 CTAs/SM.
// QK via wmma into sS; softmax; PV via raw m16n8k16 with LDSM4T on V.
// Single KV buffer; co-resident CTA hides load/barrier latency.
// ---------------------------------------------------------------------------
#include <mma.h>
using namespace nvcuda;

#define QLD 136      // halves
#define SLD 68       // floats
#define PLD 72       // halves

#define OFF_QH 0         // 17408
#define OFF_K  17408     // 17408
#define OFF_V  34816     // 17408
#define OFF_S  52224     // 64*68*4 = 17408
#define OFF_P  69632     // 64*72*2 = 9216
#define OFF_M  78848
#define OFF_L  79104
#define OFF_A  79360
#define FLASH_SMEM 79616

__global__ void __launch_bounds__(256, 2) flash_wmma(
    const __half* __restrict__ qh,
    const __half* __restrict__ kh, const __half* __restrict__ vv,
    __half* __restrict__ attn)
{
    extern __shared__ char smc[];
    __half* sQh = (__half*)(smc + OFF_QH);
    __half* sKh = (__half*)(smc + OFF_K);
    float*  sS  = (float*)(smc + OFF_S);
    __half* sP  = (__half*)(smc + OFF_P);
    float*  sM  = (float*)(smc + OFF_M);
    float*  sL  = (float*)(smc + OFF_L);
    float*  sA  = (float*)(smc + OFF_A);

    const int h     = blockIdx.x;
    const int ptile = (int)gridDim.y - 1 - blockIdx.y;
    const int m0    = ptile << 6;
    const int kvh   = h >> 3;
    const int tid   = threadIdx.x;
    const int wid   = tid >> 5;
    const int lane  = tid & 31;
    const int rs    = wid >> 1;      // 16-row slab (0..3)
    const int ch    = wid & 1;       // 64-col half (QK: 32-kcol half)
    const float scale = 0.08838834764831845f;

    // Persistent O fragments: 8 x (n8) covering 16 rows x 64 cols per warp
    float accO[8][4];
#pragma unroll
    for (int f = 0; f < 8; f++)
#pragma unroll
        for (int r = 0; r < 4; r++) accO[f][r] = 0.0f;

    auto load_kv = [&](int kb) {
        const int k0g = kb << 6;
        const uint32_t base = smem_u32(smc) + OFF_K;
#pragma unroll
        for (int i = 0; i < 4; i++) {
            int idx = tid + (i << 8);
            int r = idx >> 4, c = idx & 15;
            size_t so = (size_t)(k0g + r) * NKVD + kvh * HD + (c << 3);
            uint32_t off = r * (QLD * 2) + (c << 4);
            cpa16(base + off,         kh + so);
            cpa16(base + 17408 + off, vv + so);
        }
        CPA_COMMIT();
    };

    // Q load
    {
        uint32_t dqh = smem_u32(sQh);
#pragma unroll
        for (int i = 0; i < 4; i++) {
            int idx = tid + (i << 8);
            int r = idx >> 4, c = idx & 15;
            size_t so = (size_t)(m0 + r) * NQ + h * HD + (c << 3);
            uint32_t off = r * (QLD * 2) + (c << 4);
            cpa16(dqh + off, qh + so);
        }
        CPA_COMMIT();
    }
    if (tid < 64) { sM[tid] = -1e30f; sL[tid] = 0.f; }

    for (int kb = 0; kb <= ptile; kb++) {
        const int k0g = kb << 6;

        load_kv(kb);
        CPA_WAIT0();
        __syncthreads();

        // --- QK^T (wmma, scores -> sS 64x64) ---
        {
            wmma::fragment<wmma::accumulator, 16, 16, 16, float> accS[2];
            wmma::fill_fragment(accS[0], 0.0f);
            wmma::fill_fragment(accS[1], 0.0f);
#pragma unroll
            for (int k0 = 0; k0 < 128; k0 += 16) {
                wmma::fragment<wmma::matrix_a, 16, 16, 16, __half, wmma::row_major> ah;
                wmma::load_matrix_sync(ah, sQh + rs * 16 * QLD + k0, QLD);
#pragma unroll
                for (int j = 0; j < 2; j++) {
                    wmma::fragment<wmma::matrix_b, 16, 16, 16, __half, wmma::col_major> bh;
                    int kcol = ch * 32 + j * 16;
                    wmma::load_matrix_sync(bh, sKh + kcol * QLD + k0, QLD);
                    wmma::mma_sync(accS[j], ah, bh, accS[j]);
                }
            }
#pragma unroll
            for (int j = 0; j < 2; j++)
                wmma::store_matrix_sync(sS + rs * 16 * SLD + ch * 32 + j * 16,
                                        accS[j], SLD, wmma::mem_row_major);
        }
        __syncthreads();

        // --- online softmax ---
        {
            const int r  = tid >> 2;
            const int q4 = tid & 3;
            float* srow = sS + r * SLD + q4 * 16;
            const int qglob = m0 + r;
            const int kbase = k0g + q4 * 16;

            float vals[16];
            float mx = -1e30f;
#pragma unroll
            for (int j = 0; j < 16; j++) {
                float s = srow[j];
                s = (kbase + j <= qglob) ? s * scale : -1e30f;
                vals[j] = s;
                mx = fmaxf(mx, s);
            }
            mx = fmaxf(mx, __shfl_xor_sync(0xffffffffu, mx, 1));
            mx = fmaxf(mx, __shfl_xor_sync(0xffffffffu, mx, 2));

            float mold = sM[r];
            float mnew = fmaxf(mold, mx);
            float alpha = fexp(mold - mnew);

            __half* prow = sP + r * PLD + q4 * 16;
            float lsum = 0.f;
#pragma unroll
            for (int j = 0; j < 16; j++) {
                float p = fexp(vals[j] - mnew);
                prow[j] = __float2half(p);
                lsum += p;
            }
            lsum += __shfl_xor_sync(0xffffffffu, lsum, 1);
            lsum += __shfl_xor_sync(0xffffffffu, lsum, 2);

            if (q4 == 0) {
                sM[r] = mnew;
                sL[r] = sL[r] * alpha + lsum;
                sA[r] = alpha;
            }
        }
        __syncthreads();

        // --- rescale O (registers) and accumulate P @ V (raw mma) ---
        {
            const int qr = rs * 16 + (lane >> 2);
            const float a0 = sA[qr], a1 = sA[qr + 8];
#pragma unroll
            for (int f = 0; f < 8; f++) {
                accO[f][0] *= a0; accO[f][1] *= a0;
                accO[f][2] *= a1; accO[f][3] *= a1;
            }

            const uint32_t pA = smem_u32(smc) + OFF_P
                              + (rs * 16 + (lane & 15)) * (PLD * 2)
                              + ((lane >> 4) << 4);
            const uint32_t vB = smem_u32(smc) + OFF_V
                              + (lane & 15) * (QLD * 2)
                              + (ch * 64 + ((lane >> 4) << 3)) * 2;
#pragma unroll
            for (int kk = 0; kk < 4; kk++) {
                uint32_t pa[4];
                LDSM4(pa, pA + kk * 32);
                const uint32_t vk = vB + kk * 16 * (QLD * 2);
#pragma unroll
                for (int nf = 0; nf < 4; nf++) {
                    uint32_t bt[4];
                    LDSM4T(bt, vk + nf * 32);
                    mma16816f(accO[nf * 2],     pa, bt[0], bt[1]);
                    mma16816f(accO[nf * 2 + 1], pa, bt[2], bt[3]);
                }
            }
        }
        __syncthreads();   // V reads done before next load_kv overwrites
    }

    // Epilogue: normalize, write fp16 (half2 stores)
    {
        const int qr = rs * 16 + (lane >> 2);
        const float l0 = 1.0f / sL[qr], l1 = 1.0f / sL[qr + 8];
        const size_t r0 = (size_t)(m0 + qr) * NQ + h * HD;
        const size_t r1 = r0 + 8 * NQ;
#pragma unroll
        for (int f = 0; f < 8; f++) {
            const int col = ch * 64 + (f >> 1) * 16 + (f & 1) * 8 + (lane & 3) * 2;
            *(__half2*)(attn + r0 + col) = __halves2half2(
                __float2half(accO[f][0] * l0), __float2half(accO[f][1] * l0));
            *(__half2*)(attn + r1 + col) = __halves2half2(
                __float2half(accO[f][2] * l1), __float2half(accO[f][3] * l1));
        }
    }
}

// ---------------------------------------------------------------------------
extern "C" void kernel_launch(void* const* d_in, const int* in_sizes, int n_in,
                              void* d_out, int out_size)
{
    (void)in_sizes; (void)n_in; (void)out_size;
    const float* x  = (const float*)d_in[0];
    const float* wq = (const float*)d_in[1];
    const float* wk = (const float*)d_in[2];
    const float* wv = (const float*)d_in[3];
    const float* wo = (const float*)d_in[4];
    const float* qn = (const float*)d_in[5];
    const float* kn = (const float*)d_in[6];
    const float* cs = (const float*)d_in[7];
    const float* sn = (const float*)d_in[8];
    float* out = (float*)d_out;

    float* qkv;
    cudaGetSymbolAddress((void**)&qkv, g_qkv);

    __half *x16, *w16q, *w16k, *w16v, *wo16, *at16;
    cudaGetSymbolAddress((void**)&x16,  g_x16);
    cudaGetSymbolAddress((void**)&w16q, g_w16q);
    cudaGetSymbolAddress((void**)&w16k, g_w16k);
    cudaGetSymbolAddress((void**)&w16v, g_w16v);
    cudaGetSymbolAddress((void**)&wo16, g_wo16);
    cudaGetSymbolAddress((void**)&at16, g_at16);

    __half *q16h, *k16h, *v16;
    cudaGetSymbolAddress((void**)&q16h, g_q16h);
    cudaGetSymbolAddress((void**)&k16h, g_k16h);
    cudaGetSymbolAddress((void**)&v16,  g_v16);

    cudaFuncSetAttribute(gemm_mma_f16t,
                         cudaFuncAttributeMaxDynamicSharedMemorySize, GEMM_SMEM);
    cudaFuncSetAttribute(flash_wmma,
                         cudaFuncAttributeMaxDynamicSharedMemorySize, FLASH_SMEM);

    // Pure streaming fp32 -> fp16 converts (no transposes)
    cvt_f16v<<<(S_LEN * HID / 4 + 255) / 256, 256>>>(
        (const float4*)x, (uint2*)x16, S_LEN * HID / 4);
    cvt_f16v<<<(HID * NQ / 4 + 255) / 256, 256>>>(
        (const float4*)wq, (uint2*)w16q, HID * NQ / 4);
    cvt_f16v<<<(HID * NKVD / 4 + 255) / 256, 256>>>(
        (const float4*)wk, (uint2*)w16k, HID * NKVD / 4);
    cvt_f16v<<<(HID * NKVD / 4 + 255) / 256, 256>>>(
        (const float4*)wv, (uint2*)w16v, HID * NKVD / 4);
    cvt_f16v<<<(NQ * HID / 4 + 255) / 256, 256>>>(
        (const float4*)wo, (uint2*)wo16, NQ * HID / 4);

    // Fused QKV projection
    gemm_mma_f16t<<<dim3(NQKV / 128, S_LEN / 128), 256, GEMM_SMEM>>>(
        x16, w16q, w16k, w16v, NQ, NKVD, NQ, NKVD, qkv, NQKV, HID);

    // RMSNorm + RoPE -> fp16; V -> fp16
    rmsnorm_rope_f16<<<S_LEN * NH,  128>>>(qkv, 0,  qn, cs, sn, NH,  q16h);
    rmsnorm_rope_f16<<<S_LEN * NKV, 128>>>(qkv, NQ, kn, cs, sn, NKV, k16h);
    cvt_v16<<<(S_LEN * NKVD) / 256, 256>>>(qkv, v16);

    // Flash attention (2 CTAs/SM, O in registers) -> fp16
    flash_wmma<<<dim3(NH, S_LEN / 64), 256, FLASH_SMEM>>>(
        q16h, k16h, v16, at16);

    // Output projection
    gemm_mma_f16t<<<dim3(HID / 128, S_LEN / 128), 256, GEMM_SMEM>>>(
        at16, wo16, wo16, wo16, HID, HID, HID, HID, out, HID, NQ);
}

// round 16
// speedup vs baseline: 2.1952x; 1.0036x over previous
#include <cuda_runtime.h>
#include <cuda_bf16.h>
#include <cuda_fp16.h>
#include <cstdint>
#include <math.h>

#define S_LEN 2048
#define HID   2048
#define NH    32
#define NKV   4
#define HD    128
#define NQ    (NH * HD)    // 4096
#define NKVD  (NKV * HD)   // 512
#define NQKV  (NQ + 2 * NKVD)  // 5120

// ---------------------------------------------------------------------------
// Scratch (device globals — no allocation allowed)
// ---------------------------------------------------------------------------
__device__ float g_qkv[S_LEN * NQKV];    // only Q|K columns written (V bypassed)

__device__ __half g_x16[S_LEN * HID];
__device__ __half g_w16q[HID * NQ];      // fp16 weights, original [K][N] layout
__device__ __half g_w16k[HID * NKVD];
__device__ __half g_w16v[HID * NKVD];
__device__ __half g_wo16[NQ * HID];
__device__ __half g_at16[S_LEN * NQ];

__device__ __half g_q16h[S_LEN * NQ];
__device__ __half g_k16h[S_LEN * NKVD];
__device__ __half g_v16[S_LEN * NKVD];

// ---------------------------------------------------------------------------
// helpers
// ---------------------------------------------------------------------------
__device__ __forceinline__ uint32_t smem_u32(const void* p) {
    uint32_t a;
    asm("{ .reg .u64 t; cvta.to.shared.u64 t, %1; cvt.u32.u64 %0, t; }"
        : "=r"(a) : "l"(p));
    return a;
}

__device__ __forceinline__ void cpa16(uint32_t dst, const void* src) {
    asm volatile(
        "{\n\t.reg .u64 g;\n\tcvta.to.global.u64 g, %1;\n\t"
        "cp.async.cg.shared.global [%0], [g], 16;\n\t}"
        :: "r"(dst), "l"(src) : "memory");
}
#define CPA_COMMIT() asm volatile("cp.async.commit_group;" ::: "memory")
#define CPA_WAIT2()  asm volatile("cp.async.wait_group 2;" ::: "memory")
#define CPA_WAIT1()  asm volatile("cp.async.wait_group 1;" ::: "memory")
#define CPA_WAIT0()  asm volatile("cp.async.wait_group 0;" ::: "memory")

#define LDSM4(r, addr) \
    asm volatile("ldmatrix.sync.aligned.m8n8.x4.shared.b16 {%0,%1,%2,%3}, [%4];" \
        : "=r"((r)[0]), "=r"((r)[1]), "=r"((r)[2]), "=r"((r)[3]) : "r"(addr))

#define LDSM4T(r, addr) \
    asm volatile("ldmatrix.sync.aligned.m8n8.x4.trans.shared.b16 {%0,%1,%2,%3}, [%4];" \
        : "=r"((r)[0]), "=r"((r)[1]), "=r"((r)[2]), "=r"((r)[3]) : "r"(addr))

__device__ __forceinline__ void mma16816f(float* d, const uint32_t* a,
                                          uint32_t b0, uint32_t b1) {
    asm volatile(
        "mma.sync.aligned.m16n8k16.row.col.f32.f16.f16.f32 "
        "{%0,%1,%2,%3}, {%4,%5,%6,%7}, {%8,%9}, {%0,%1,%2,%3};"
        : "+f"(d[0]), "+f"(d[1]), "+f"(d[2]), "+f"(d[3])
        : "r"(a[0]), "r"(a[1]), "r"(a[2]), "r"(a[3]), "r"(b0), "r"(b1));
}

// Fast exp on the FFMA pipe. Rel err < 3e-6 on [-87, 0].
__device__ __forceinline__ float fexp(float x) {
    x = fmaxf(x, -87.0f);
    float z  = fmaf(x, 1.44269504089f, 12582912.0f);
    float nf = z - 12582912.0f;
    float f  = fmaf(x, 1.44269504089f, -nf);
    float p  = 1.333355815e-3f;
    p = fmaf(p, f, 9.618129107e-3f);
    p = fmaf(p, f, 5.550410866e-2f);
    p = fmaf(p, f, 2.402265069e-1f);
    p = fmaf(p, f, 6.931471806e-1f);
    p = fmaf(p, f, 1.0f);
    int n = __float_as_int(z) - 0x4B400000;
    return __int_as_float(__float_as_int(p) + (n << 23));
}

// ---------------------------------------------------------------------------
// Merged fp32 -> fp16 convert over 5 buffers (one launch)
// ---------------------------------------------------------------------------
__global__ void cvt_all(
    const float4* __restrict__ s0, uint2* __restrict__ d0, int c0,
    const float4* __restrict__ s1, uint2* __restrict__ d1, int c1,
    const float4* __restrict__ s2, uint2* __restrict__ d2, int c2,
    const float4* __restrict__ s3, uint2* __restrict__ d3, int c3,
    const float4* __restrict__ s4, uint2* __restrict__ d4, int c4)
{
    int i = blockIdx.x * blockDim.x + threadIdx.x;
    const float4* s; uint2* d; int idx = i;
    if (idx < c0) { s = s0; d = d0; }
    else {
        idx -= c0;
        if (idx < c1) { s = s1; d = d1; }
        else {
            idx -= c1;
            if (idx < c2) { s = s2; d = d2; }
            else {
                idx -= c2;
                if (idx < c3) { s = s3; d = d3; }
                else {
                    idx -= c3;
                    if (idx >= c4) return;
                    s = s4; d = d4;
                }
            }
        }
    }
    float4 v = s[idx];
    __half2 a = __halves2half2(__float2half(v.x), __float2half(v.y));
    __half2 b = __halves2half2(__float2half(v.z), __float2half(v.w));
    uint2 r;
    r.x = *(uint32_t*)&a; r.y = *(uint32_t*)&b;
    d[idx] = r;
}

// ---------------------------------------------------------------------------
// Raw-HMMA fp16 GEMM with row-major [K][N] B, 4-stage cp.async pipeline.
// C[m][n] = sum_k A[m][k] * B[k][n]. CTA 128x128, 8 warps (2x4), warp 64x32.
// V-region columns (n0 >= nq+nkv, when v16 != null) are written fp16 direct.
// ---------------------------------------------------------------------------
#define RPAD_A 80
#define ATILE  (128 * RPAD_A)            // 10240
#define BLDB   272
#define BTILE  (32 * BLDB)               // 8704
#define STG_T  (ATILE + BTILE)           // 18944
#define GEMM_SMEM (4 * STG_T)            // 75776 (2 CTAs/SM)

__global__ void __launch_bounds__(256, 2) gemm_mma_f16t(
    const __half* __restrict__ A,
    const __half* __restrict__ B0, const __half* __restrict__ B1,
    const __half* __restrict__ B2,
    int nq, int nkv, int ld0, int ldkv,
    float* __restrict__ C, __half* __restrict__ v16, int N, int K)
{
    extern __shared__ char smraw[];
    const int tid  = threadIdx.x;
    const int wid  = tid >> 5, lane = tid & 31;
    const int m0 = blockIdx.y << 7, n0 = blockIdx.x << 7;
    const int wm = wid >> 2;
    const int wn = wid & 3;

    const uint32_t sbase = smem_u32(smraw);

    const __half* Bp; int ldB, nloc;
    if (n0 < nq)            { Bp = B0; ldB = ld0;  nloc = n0; }
    else if (n0 < nq + nkv) { Bp = B1; ldB = ldkv; nloc = n0 - nq; }
    else                    { Bp = B2; ldB = ldkv; nloc = n0 - nq - nkv; }

    float acc[4][4][4];
#pragma unroll
    for (int i = 0; i < 4; i++)
#pragma unroll
        for (int j = 0; j < 4; j++)
#pragma unroll
            for (int r = 0; r < 4; r++) acc[i][j][r] = 0.0f;

    const uint32_t lrow = lane & 15;
    const uint32_t lkof = (lane >> 4) << 4;
    const int nck = K >> 5;

    auto load_stage = [&](int ck, int st) {
        const int k0 = ck << 5;
        const uint32_t sb = sbase + st * STG_T;
#pragma unroll
        for (int i = 0; i < 2; i++) {
            int idx = (i << 8) + tid;
            int row = idx >> 2, c = idx & 3;
            cpa16(sb + row * RPAD_A + c * 16,
                  A + (size_t)(m0 + row) * K + k0 + c * 8);
        }
#pragma unroll
        for (int i = 0; i < 2; i++) {
            int idx = (i << 8) + tid;
            int row = idx >> 4, c = idx & 15;
            cpa16(sb + ATILE + row * BLDB + c * 16,
                  Bp + (size_t)(k0 + row) * ldB + nloc + c * 8);
        }
        CPA_COMMIT();
    };

    load_stage(0, 0);
    load_stage(1, 1);
    load_stage(2, 2);

    int s = 0;
    for (int ck = 0; ck < nck; ck++) {
        const int rem = nck - 1 - ck;
        if (rem >= 2)      { CPA_WAIT2(); }
        else if (rem == 1) { CPA_WAIT1(); }
        else               { CPA_WAIT0(); }
        __syncthreads();
        if (ck + 3 < nck) {
            int s3 = s + 3; if (s3 >= 4) s3 -= 4;
            load_stage(ck + 3, s3);
        }

        const uint32_t sb = sbase + s * STG_T;
        const uint32_t ab = sb + (wm * 64 + lrow) * RPAD_A + lkof;
        const uint32_t bb = sb + ATILE + (lane & 15) * BLDB
                          + (wn * 32 + ((lane >> 4) << 3)) * 2;

#pragma unroll
        for (int kk = 0; kk < 2; kk++) {
            const uint32_t koA = kk * 32;
            const uint32_t koB = kk * 16 * BLDB;
            uint32_t bt[2][4];
            LDSM4T(bt[0], bb + koB);
            LDSM4T(bt[1], bb + koB + 32);
#pragma unroll
            for (int mt = 0; mt < 4; mt++) {
                uint32_t ah[4];
                LDSM4(ah, ab + mt * 16 * RPAD_A + koA);
#pragma unroll
                for (int nt = 0; nt < 4; nt++) {
                    const int j = nt >> 1, g = nt & 1;
                    mma16816f(acc[mt][nt], ah, bt[j][g * 2], bt[j][g * 2 + 1]);
                }
            }
        }
        if (++s >= 4) s -= 4;
    }

    const int erow = (lane >> 2);
    const int ecol = (lane & 3) << 1;

    if (v16 && n0 >= nq + nkv) {
        // V region: direct fp16 store into v16 [S][NKVD]
        const int vc0 = n0 - (nq + nkv);
#pragma unroll
        for (int mt = 0; mt < 4; mt++) {
#pragma unroll
            for (int nt = 0; nt < 4; nt++) {
                const int r = m0 + wm * 64 + mt * 16 + erow;
                const int c = vc0 + wn * 32 + nt * 8 + ecol;
                *(__half2*)(v16 + (size_t)r * NKVD + c) = __halves2half2(
                    __float2half(acc[mt][nt][0]), __float2half(acc[mt][nt][1]));
                *(__half2*)(v16 + (size_t)(r + 8) * NKVD + c) = __halves2half2(
                    __float2half(acc[mt][nt][2]), __float2half(acc[mt][nt][3]));
            }
        }
        return;
    }

#pragma unroll
    for (int mt = 0; mt < 4; mt++) {
#pragma unroll
        for (int nt = 0; nt < 4; nt++) {
            const int r = m0 + wm * 64 + mt * 16 + erow;
            const int c = n0 + wn * 32 + nt * 8 + ecol;
            *(float2*)(C + (size_t)r * N + c) =
                make_float2(acc[mt][nt][0], acc[mt][nt][1]);
            *(float2*)(C + (size_t)(r + 8) * N + c) =
                make_float2(acc[mt][nt][2], acc[mt][nt][3]);
        }
    }
}

// ---------------------------------------------------------------------------
// Fused RMSNorm + RoPE (unchanged)
// ---------------------------------------------------------------------------
__global__ __launch_bounds__(128) void rmsnorm_rope_f16(
    const float* __restrict__ qkv, int colOff, const float* __restrict__ w,
    const float* __restrict__ cs, const float* __restrict__ sn, int heads,
    __half* __restrict__ oh)
{
    const int b = blockIdx.x;
    const int s = b / heads;
    const int h = b - s * heads;
    const int d = threadIdx.x;

    const size_t io = (size_t)s * NQKV + colOff + h * HD;
    const size_t oo = ((size_t)s * heads + h) * HD;
    float v = qkv[io + d];

    float ssq = v * v;
#pragma unroll
    for (int off = 16; off > 0; off >>= 1)
        ssq += __shfl_xor_sync(0xffffffffu, ssq, off);

    __shared__ float red[4];
    __shared__ float sh[HD];
    if ((d & 31) == 0) red[d >> 5] = ssq;
    __syncthreads();
    float tot = red[0] + red[1] + red[2] + red[3];

    float xn = v * rsqrtf(tot * (1.0f / HD) + 1e-6f) * w[d];
    sh[d] = xn;
    __syncthreads();

    float partner = (d < 64) ? -sh[d + 64] : sh[d - 64];
    float res = xn * cs[s * HD + d] + partner * sn[s * HD + d];

    oh[oo + d] = __float2half(res);
}

// ---------------------------------------------------------------------------
// Flash attention v2 (R15 proven): O in registers, 80 KB smem, 2 CTAs/SM.
// ---------------------------------------------------------------------------
#include <mma.h>
using namespace nvcuda;

#define QLD 136      // halves
#define SLD 68       // floats
#define PLD 72       // halves

#define OFF_QH 0         // 17408
#define OFF_K  17408     // 17408
#define OFF_V  34816     // 17408
#define OFF_S  52224     // 64*68*4 = 17408
#define OFF_P  69632     // 64*72*2 = 9216
#define OFF_M  78848
#define OFF_L  79104
#define OFF_A  79360
#define FLASH_SMEM 79616

__global__ void __launch_bounds__(256, 2) flash_wmma(
    const __half* __restrict__ qh,
    const __half* __restrict__ kh, const __half* __restrict__ vv,
    __half* __restrict__ attn)
{
    extern __shared__ char smc[];
    __half* sQh = (__half*)(smc + OFF_QH);
    __half* sKh = (__half*)(smc + OFF_K);
    float*  sS  = (float*)(smc + OFF_S);
    __half* sP  = (__half*)(smc + OFF_P);
    float*  sM  = (float*)(smc + OFF_M);
    float*  sL  = (float*)(smc + OFF_L);
    float*  sA  = (float*)(smc + OFF_A);

    const int h     = blockIdx.x;
    const int ptile = (int)gridDim.y - 1 - blockIdx.y;
    const int m0    = ptile << 6;
    const int kvh   = h >> 3;
    const int tid   = threadIdx.x;
    const int wid   = tid >> 5;
    const int lane  = tid & 31;
    const int rs    = wid >> 1;
    const int ch    = wid & 1;
    const float scale = 0.08838834764831845f;

    float accO[8][4];
#pragma unroll
    for (int f = 0; f < 8; f++)
#pragma unroll
        for (int r = 0; r < 4; r++) accO[f][r] = 0.0f;

    auto load_kv = [&](int kb) {
        const int k0g = kb << 6;
        const uint32_t base = smem_u32(smc) + OFF_K;
#pragma unroll
        for (int i = 0; i < 4; i++) {
            int idx = tid + (i << 8);
            int r = idx >> 4, c = idx & 15;
            size_t so = (size_t)(k0g + r) * NKVD + kvh * HD + (c << 3);
            uint32_t off = r * (QLD * 2) + (c << 4);
            cpa16(base + off,         kh + so);
            cpa16(base + 17408 + off, vv + so);
        }
        CPA_COMMIT();
    };

    {
        uint32_t dqh = smem_u32(sQh);
#pragma unroll
        for (int i = 0; i < 4; i++) {
            int idx = tid + (i << 8);
            int r = idx >> 4, c = idx & 15;
            size_t so = (size_t)(m0 + r) * NQ + h * HD + (c << 3);
            uint32_t off = r * (QLD * 2) + (c << 4);
            cpa16(dqh + off, qh + so);
        }
        CPA_COMMIT();
    }
    if (tid < 64) { sM[tid] = -1e30f; sL[tid] = 0.f; }

    for (int kb = 0; kb <= ptile; kb++) {
        const int k0g = kb << 6;

        load_kv(kb);
        CPA_WAIT0();
        __syncthreads();

        // --- QK^T ---
        {
            wmma::fragment<wmma::accumulator, 16, 16, 16, float> accS[2];
            wmma::fill_fragment(accS[0], 0.0f);
            wmma::fill_fragment(accS[1], 0.0f);
#pragma unroll
            for (int k0 = 0; k0 < 128; k0 += 16) {
                wmma::fragment<wmma::matrix_a, 16, 16, 16, __half, wmma::row_major> ah;
                wmma::load_matrix_sync(ah, sQh + rs * 16 * QLD + k0, QLD);
#pragma unroll
                for (int j = 0; j < 2; j++) {
                    wmma::fragment<wmma::matrix_b, 16, 16, 16, __half, wmma::col_major> bh;
                    int kcol = ch * 32 + j * 16;
                    wmma::load_matrix_sync(bh, sKh + kcol * QLD + k0, QLD);
                    wmma::mma_sync(accS[j], ah, bh, accS[j]);
                }
            }
#pragma unroll
            for (int j = 0; j < 2; j++)
                wmma::store_matrix_sync(sS + rs * 16 * SLD + ch * 32 + j * 16,
                                        accS[j], SLD, wmma::mem_row_major);
        }
        __syncthreads();

        // --- online softmax ---
        {
            const int r  = tid >> 2;
            const int q4 = tid & 3;
            float* srow = sS + r * SLD + q4 * 16;
            const int qglob = m0 + r;
            const int kbase = k0g + q4 * 16;

            float vals[16];
            float mx = -1e30f;
#pragma unroll
            for (int j = 0; j < 16; j++) {
                float s = srow[j];
                s = (kbase + j <= qglob) ? s * scale : -1e30f;
                vals[j] = s;
                mx = fmaxf(mx, s);
            }
            mx = fmaxf(mx, __shfl_xor_sync(0xffffffffu, mx, 1));
            mx = fmaxf(mx, __shfl_xor_sync(0xffffffffu, mx, 2));

            float mold = sM[r];
            float mnew = fmaxf(mold, mx);
            float alpha = fexp(mold - mnew);

            __half* prow = sP + r * PLD + q4 * 16;
            float lsum = 0.f;
#pragma unroll
            for (int j = 0; j < 16; j++) {
                float p = fexp(vals[j] - mnew);
                prow[j] = __float2half(p);
                lsum += p;
            }
            lsum += __shfl_xor_sync(0xffffffffu, lsum, 1);
            lsum += __shfl_xor_sync(0xffffffffu, lsum, 2);

            if (q4 == 0) {
                sM[r] = mnew;
                sL[r] = sL[r] * alpha + lsum;
                sA[r] = alpha;
            }
        }
        __syncthreads();

        // --- rescale O (registers) and accumulate P @ V ---
        {
            const int qr = rs * 16 + (lane >> 2);
            const float a0 = sA[qr], a1 = sA[qr + 8];
#pragma unroll
            for (int f = 0; f < 8; f++) {
                accO[f][0] *= a0; accO[f][1] *= a0;
                accO[f][2] *= a1; accO[f][3] *= a1;
            }

            const uint32_t pA = smem_u32(smc) + OFF_P
                              + (rs * 16 + (lane & 15)) * (PLD * 2)
                              + ((lane >> 4) << 4);
            const uint32_t vB = smem_u32(smc) + OFF_V
                              + (lane & 15) * (QLD * 2)
                              + (ch * 64 + ((lane >> 4) << 3)) * 2;
#pragma unroll
            for (int kk = 0; kk < 4; kk++) {
                uint32_t pa[4];
                LDSM4(pa, pA + kk * 32);
                const uint32_t vk = vB + kk * 16 * (QLD * 2);
#pragma unroll
                for (int nf = 0; nf < 4; nf++) {
                    uint32_t bt[4];
                    LDSM4T(bt, vk + nf * 32);
                    mma16816f(accO[nf * 2],     pa, bt[0], bt[1]);
                    mma16816f(accO[nf * 2 + 1], pa, bt[2], bt[3]);
                }
            }
        }
        __syncthreads();
    }

    // Epilogue
    {
        const int qr = rs * 16 + (lane >> 2);
        const float l0 = 1.0f / sL[qr], l1 = 1.0f / sL[qr + 8];
        const size_t r0 = (size_t)(m0 + qr) * NQ + h * HD;
        const size_t r1 = r0 + 8 * NQ;
#pragma unroll
        for (int f = 0; f < 8; f++) {
            const int col = ch * 64 + (f >> 1) * 16 + (f & 1) * 8 + (lane & 3) * 2;
            *(__half2*)(attn + r0 + col) = __halves2half2(
                __float2half(accO[f][0] * l0), __float2half(accO[f][1] * l0));
            *(__half2*)(attn + r1 + col) = __halves2half2(
                __float2half(accO[f][2] * l1), __float2half(accO[f][3] * l1));
        }
    }
}

// ---------------------------------------------------------------------------
extern "C" void kernel_launch(void* const* d_in, const int* in_sizes, int n_in,
                              void* d_out, int out_size)
{
    (void)in_sizes; (void)n_in; (void)out_size;
    const float* x  = (const float*)d_in[0];
    const float* wq = (const float*)d_in[1];
    const float* wk = (const float*)d_in[2];
    const float* wv = (const float*)d_in[3];
    const float* wo = (const float*)d_in[4];
    const float* qn = (const float*)d_in[5];
    const float* kn = (const float*)d_in[6];
    const float* cs = (const float*)d_in[7];
    const float* sn = (const float*)d_in[8];
    float* out = (float*)d_out;

    float* qkv;
    cudaGetSymbolAddress((void**)&qkv, g_qkv);

    __half *x16, *w16q, *w16k, *w16v, *wo16, *at16;
    cudaGetSymbolAddress((void**)&x16,  g_x16);
    cudaGetSymbolAddress((void**)&w16q, g_w16q);
    cudaGetSymbolAddress((void**)&w16k, g_w16k);
    cudaGetSymbolAddress((void**)&w16v, g_w16v);
    cudaGetSymbolAddress((void**)&wo16, g_wo16);
    cudaGetSymbolAddress((void**)&at16, g_at16);

    __half *q16h, *k16h, *v16;
    cudaGetSymbolAddress((void**)&q16h, g_q16h);
    cudaGetSymbolAddress((void**)&k16h, g_k16h);
    cudaGetSymbolAddress((void**)&v16,  g_v16);

    cudaFuncSetAttribute(gemm_mma_f16t,
                         cudaFuncAttributeMaxDynamicSharedMemorySize, GEMM_SMEM);
    cudaFuncSetAttribute(flash_wmma,
                         cudaFuncAttributeMaxDynamicSharedMemorySize, FLASH_SMEM);

    // One merged fp32 -> fp16 convert launch (x + 4 weight matrices)
    {
        const int c0 = S_LEN * HID / 4;      // x
        const int c1 = HID * NQ / 4;         // wq
        const int c2 = HID * NKVD / 4;       // wk
        const int c3 = HID * NKVD / 4;       // wv
        const int c4 = NQ * HID / 4;         // wo
        const int total = c0 + c1 + c2 + c3 + c4;
        cvt_all<<<(total + 255) / 256, 256>>>(
            (const float4*)x,  (uint2*)x16,  c0,
            (const float4*)wq, (uint2*)w16q, c1,
            (const float4*)wk, (uint2*)w16k, c2,
            (const float4*)wv, (uint2*)w16v, c3,
            (const float4*)wo, (uint2*)wo16, c4);
    }

    // Fused QKV projection (V columns stream straight to fp16 v16)
    gemm_mma_f16t<<<dim3(NQKV / 128, S_LEN / 128), 256, GEMM_SMEM>>>(
        x16, w16q, w16k, w16v, NQ, NKVD, NQ, NKVD, qkv, v16, NQKV, HID);

    // RMSNorm + RoPE -> fp16
    rmsnorm_rope_f16<<<S_LEN * NH,  128>>>(qkv, 0,  qn, cs, sn, NH,  q16h);
    rmsnorm_rope_f16<<<S_LEN * NKV, 128>>>(qkv, NQ, kn, cs, sn, NKV, k16h);

    // Flash attention (2 CTAs/SM, O in registers) -> fp16
    flash_wmma<<<dim3(NH, S_LEN / 64), 256, FLASH_SMEM>>>(
        q16h, k16h, v16, at16);

    // Output projection
    gemm_mma_f16t<<<dim3(HID / 128, S_LEN / 128), 256, GEMM_SMEM>>>(
        at16, wo16, wo16, wo16, HID, HID, HID, HID, out, (half*)0, HID, NQ);
}

// round 17
// speedup vs baseline: 2.2489x; 1.0245x over previous
#include <cuda_runtime.h>
#include <cuda_bf16.h>
#include <cuda_fp16.h>
#include <cstdint>
#include <math.h>

#define S_LEN 2048
#define HID   2048
#define NH    32
#define NKV   4
#define HD    128
#define NQ    (NH * HD)    // 4096
#define NKVD  (NKV * HD)   // 512
#define NQKV  (NQ + 2 * NKVD)  // 5120

// ---------------------------------------------------------------------------
// Scratch (device globals — no allocation allowed)
// ---------------------------------------------------------------------------
__device__ float g_qkv[S_LEN * NQKV];    // only Q|K columns written (V bypassed)

__device__ __half g_x16[S_LEN * HID];
__device__ __half g_w16q[HID * NQ];      // fp16 weights, original [K][N] layout
__device__ __half g_w16k[HID * NKVD];
__device__ __half g_w16v[HID * NKVD];
__device__ __half g_wo16[NQ * HID];
__device__ __half g_at16[S_LEN * NQ];

__device__ __half g_q16h[S_LEN * NQ];
__device__ __half g_k16h[S_LEN * NKVD];
__device__ __half g_v16[S_LEN * NKVD];

// ---------------------------------------------------------------------------
// helpers
// ---------------------------------------------------------------------------
__device__ __forceinline__ uint32_t smem_u32(const void* p) {
    uint32_t a;
    asm("{ .reg .u64 t; cvta.to.shared.u64 t, %1; cvt.u32.u64 %0, t; }"
        : "=r"(a) : "l"(p));
    return a;
}

__device__ __forceinline__ void cpa16(uint32_t dst, const void* src) {
    asm volatile(
        "{\n\t.reg .u64 g;\n\tcvta.to.global.u64 g, %1;\n\t"
        "cp.async.cg.shared.global [%0], [g], 16;\n\t}"
        :: "r"(dst), "l"(src) : "memory");
}
#define CPA_COMMIT() asm volatile("cp.async.commit_group;" ::: "memory")
#define CPA_WAIT1()  asm volatile("cp.async.wait_group 1;" ::: "memory")
#define CPA_WAIT0()  asm volatile("cp.async.wait_group 0;" ::: "memory")

#define LDSM4(r, addr) \
    asm volatile("ldmatrix.sync.aligned.m8n8.x4.shared.b16 {%0,%1,%2,%3}, [%4];" \
        : "=r"((r)[0]), "=r"((r)[1]), "=r"((r)[2]), "=r"((r)[3]) : "r"(addr))

#define LDSM4T(r, addr) \
    asm volatile("ldmatrix.sync.aligned.m8n8.x4.trans.shared.b16 {%0,%1,%2,%3}, [%4];" \
        : "=r"((r)[0]), "=r"((r)[1]), "=r"((r)[2]), "=r"((r)[3]) : "r"(addr))

#define BAR_PAIR(id) \
    asm volatile("bar.sync %0, 64;" :: "r"(id) : "memory")

__device__ __forceinline__ void mma16816f(float* d, const uint32_t* a,
                                          uint32_t b0, uint32_t b1) {
    asm volatile(
        "mma.sync.aligned.m16n8k16.row.col.f32.f16.f16.f32 "
        "{%0,%1,%2,%3}, {%4,%5,%6,%7}, {%8,%9}, {%0,%1,%2,%3};"
        : "+f"(d[0]), "+f"(d[1]), "+f"(d[2]), "+f"(d[3])
        : "r"(a[0]), "r"(a[1]), "r"(a[2]), "r"(a[3]), "r"(b0), "r"(b1));
}

// Fast exp on the FFMA pipe. Rel err < 3e-6 on [-87, 0].
__device__ __forceinline__ float fexp(float x) {
    x = fmaxf(x, -87.0f);
    float z  = fmaf(x, 1.44269504089f, 12582912.0f);
    float nf = z - 12582912.0f;
    float f  = fmaf(x, 1.44269504089f, -nf);
    float p  = 1.333355815e-3f;
    p = fmaf(p, f, 9.618129107e-3f);
    p = fmaf(p, f, 5.550410866e-2f);
    p = fmaf(p, f, 2.402265069e-1f);
    p = fmaf(p, f, 6.931471806e-1f);
    p = fmaf(p, f, 1.0f);
    int n = __float_as_int(z) - 0x4B400000;
    return __int_as_float(__float_as_int(p) + (n << 23));
}

// ---------------------------------------------------------------------------
// Merged fp32 -> fp16 convert over 5 buffers (one launch)
// ---------------------------------------------------------------------------
__global__ void cvt_all(
    const float4* __restrict__ s0, uint2* __restrict__ d0, int c0,
    const float4* __restrict__ s1, uint2* __restrict__ d1, int c1,
    const float4* __restrict__ s2, uint2* __restrict__ d2, int c2,
    const float4* __restrict__ s3, uint2* __restrict__ d3, int c3,
    const float4* __restrict__ s4, uint2* __restrict__ d4, int c4)
{
    int i = blockIdx.x * blockDim.x + threadIdx.x;
    const float4* s; uint2* d; int idx = i;
    if (idx < c0) { s = s0; d = d0; }
    else {
        idx -= c0;
        if (idx < c1) { s = s1; d = d1; }
        else {
            idx -= c1;
            if (idx < c2) { s = s2; d = d2; }
            else {
                idx -= c2;
                if (idx < c3) { s = s3; d = d3; }
                else {
                    idx -= c3;
                    if (idx >= c4) return;
                    s = s4; d = d4;
                }
            }
        }
    }
    float4 v = s[idx];
    __half2 a = __halves2half2(__float2half(v.x), __float2half(v.y));
    __half2 b = __halves2half2(__float2half(v.z), __float2half(v.w));
    uint2 r;
    r.x = *(uint32_t*)&a; r.y = *(uint32_t*)&b;
    d[idx] = r;
}

// ---------------------------------------------------------------------------
// Raw-HMMA fp16 GEMM, row-major [K][N] B, K-chunk 64, 3-stage cp.async.
// CTA 128x128, 8 warps (2x4), warp tile 64x32. One barrier per 64-K chunk.
// V-region columns (n0 >= nq+nkv, v16 != null) stored fp16 direct.
// ---------------------------------------------------------------------------
#define RPAD_A 144                       // 128 B data + 16 pad
#define ATILE  (128 * RPAD_A)            // 18432
#define BLDB   272                       // 256 B data + 16 pad
#define BTILE  (64 * BLDB)               // 17408
#define STG_T  (ATILE + BTILE)           // 35840
#define GEMM_SMEM (3 * STG_T)            // 107520 (2 CTAs/SM: 215 KB)

__global__ void __launch_bounds__(256, 2) gemm_mma_f16t(
    const __half* __restrict__ A,
    const __half* __restrict__ B0, const __half* __restrict__ B1,
    const __half* __restrict__ B2,
    int nq, int nkv, int ld0, int ldkv,
    float* __restrict__ C, __half* __restrict__ v16, int N, int K)
{
    extern __shared__ char smraw[];
    const int tid  = threadIdx.x;
    const int wid  = tid >> 5, lane = tid & 31;
    const int m0 = blockIdx.y << 7, n0 = blockIdx.x << 7;
    const int wm = wid >> 2;
    const int wn = wid & 3;

    const uint32_t sbase = smem_u32(smraw);

    const __half* Bp; int ldB, nloc;
    if (n0 < nq)            { Bp = B0; ldB = ld0;  nloc = n0; }
    else if (n0 < nq + nkv) { Bp = B1; ldB = ldkv; nloc = n0 - nq; }
    else                    { Bp = B2; ldB = ldkv; nloc = n0 - nq - nkv; }

    float acc[4][4][4];
#pragma unroll
    for (int i = 0; i < 4; i++)
#pragma unroll
        for (int j = 0; j < 4; j++)
#pragma unroll
            for (int r = 0; r < 4; r++) acc[i][j][r] = 0.0f;

    const uint32_t lrow = lane & 15;
    const uint32_t lkof = (lane >> 4) << 4;
    const int nck = K >> 6;

    auto load_stage = [&](int ck, int st) {
        const int k0 = ck << 6;
        const uint32_t sb = sbase + st * STG_T;
        // A tile: 128 m-rows x 64 k fp16 (128 B data / 144 B row)
#pragma unroll
        for (int i = 0; i < 4; i++) {
            int idx = (i << 8) + tid;          // 0..1023
            int row = idx >> 3, c = idx & 7;
            cpa16(sb + row * RPAD_A + c * 16,
                  A + (size_t)(m0 + row) * K + k0 + c * 8);
        }
        // B tile: 64 k-rows x 128 n fp16 (256 B data / 272 B row)
#pragma unroll
        for (int i = 0; i < 4; i++) {
            int idx = (i << 8) + tid;          // 0..1023
            int row = idx >> 4, c = idx & 15;
            cpa16(sb + ATILE + row * BLDB + c * 16,
                  Bp + (size_t)(k0 + row) * ldB + nloc + c * 8);
        }
        CPA_COMMIT();
    };

    load_stage(0, 0);
    load_stage(1, 1);

    int s = 0;
    for (int ck = 0; ck < nck; ck++) {
        if (ck + 1 < nck) { CPA_WAIT1(); } else { CPA_WAIT0(); }
        __syncthreads();
        if (ck + 2 < nck) {
            int s2 = s + 2; if (s2 >= 3) s2 -= 3;
            load_stage(ck + 2, s2);
        }

        const uint32_t sb = sbase + s * STG_T;
        const uint32_t ab = sb + (wm * 64 + lrow) * RPAD_A + lkof;
        const uint32_t bb = sb + ATILE + (lane & 15) * BLDB
                          + (wn * 32 + ((lane >> 4) << 3)) * 2;

#pragma unroll
        for (int kk = 0; kk < 4; kk++) {
            const uint32_t koA = kk * 32;          // 16 k halves = 32 B
            const uint32_t koB = kk * 16 * BLDB;   // 16 k-rows
            uint32_t bt[2][4];
            LDSM4T(bt[0], bb + koB);
            LDSM4T(bt[1], bb + koB + 32);
#pragma unroll
            for (int mt = 0; mt < 4; mt++) {
                uint32_t ah[4];
                LDSM4(ah, ab + mt * 16 * RPAD_A + koA);
#pragma unroll
                for (int nt = 0; nt < 4; nt++) {
                    const int j = nt >> 1, g = nt & 1;
                    mma16816f(acc[mt][nt], ah, bt[j][g * 2], bt[j][g * 2 + 1]);
                }
            }
        }
        if (++s >= 3) s -= 3;
    }

    const int erow = (lane >> 2);
    const int ecol = (lane & 3) << 1;

    if (v16 && n0 >= nq + nkv) {
        const int vc0 = n0 - (nq + nkv);
#pragma unroll
        for (int mt = 0; mt < 4; mt++) {
#pragma unroll
            for (int nt = 0; nt < 4; nt++) {
                const int r = m0 + wm * 64 + mt * 16 + erow;
                const int c = vc0 + wn * 32 + nt * 8 + ecol;
                *(__half2*)(v16 + (size_t)r * NKVD + c) = __halves2half2(
                    __float2half(acc[mt][nt][0]), __float2half(acc[mt][nt][1]));
                *(__half2*)(v16 + (size_t)(r + 8) * NKVD + c) = __halves2half2(
                    __float2half(acc[mt][nt][2]), __float2half(acc[mt][nt][3]));
            }
        }
        return;
    }

#pragma unroll
    for (int mt = 0; mt < 4; mt++) {
#pragma unroll
        for (int nt = 0; nt < 4; nt++) {
            const int r = m0 + wm * 64 + mt * 16 + erow;
            const int c = n0 + wn * 32 + nt * 8 + ecol;
            *(float2*)(C + (size_t)r * N + c) =
                make_float2(acc[mt][nt][0], acc[mt][nt][1]);
            *(float2*)(C + (size_t)(r + 8) * N + c) =
                make_float2(acc[mt][nt][2], acc[mt][nt][3]);
        }
    }
}

// ---------------------------------------------------------------------------
// Fused RMSNorm + RoPE (unchanged)
// ---------------------------------------------------------------------------
__global__ __launch_bounds__(128) void rmsnorm_rope_f16(
    const float* __restrict__ qkv, int colOff, const float* __restrict__ w,
    const float* __restrict__ cs, const float* __restrict__ sn, int heads,
    __half* __restrict__ oh)
{
    const int b = blockIdx.x;
    const int s = b / heads;
    const int h = b - s * heads;
    const int d = threadIdx.x;

    const size_t io = (size_t)s * NQKV + colOff + h * HD;
    const size_t oo = ((size_t)s * heads + h) * HD;
    float v = qkv[io + d];

    float ssq = v * v;
#pragma unroll
    for (int off = 16; off > 0; off >>= 1)
        ssq += __shfl_xor_sync(0xffffffffu, ssq, off);

    __shared__ float red[4];
    __shared__ float sh[HD];
    if ((d & 31) == 0) red[d >> 5] = ssq;
    __syncthreads();
    float tot = red[0] + red[1] + red[2] + red[3];

    float xn = v * rsqrtf(tot * (1.0f / HD) + 1e-6f) * w[d];
    sh[d] = xn;
    __syncthreads();

    float partner = (d < 64) ? -sh[d + 64] : sh[d - 64];
    float res = xn * cs[s * HD + d] + partner * sn[s * HD + d];

    oh[oo + d] = __float2half(res);
}

// ---------------------------------------------------------------------------
// Flash attention v2 (R15 core): O in registers, 80 KB smem, 2 CTAs/SM.
// Inner QK->softmax and softmax->PV barriers are warp-pair scoped (bar.sync).
// ---------------------------------------------------------------------------
#include <mma.h>
using namespace nvcuda;

#define QLD 136      // halves
#define SLD 68       // floats
#define PLD 72       // halves

#define OFF_QH 0         // 17408
#define OFF_K  17408     // 17408
#define OFF_V  34816     // 17408
#define OFF_S  52224     // 64*68*4 = 17408
#define OFF_P  69632     // 64*72*2 = 9216
#define OFF_M  78848
#define OFF_L  79104
#define OFF_A  79360
#define FLASH_SMEM 79616

__global__ void __launch_bounds__(256, 2) flash_wmma(
    const __half* __restrict__ qh,
    const __half* __restrict__ kh, const __half* __restrict__ vv,
    __half* __restrict__ attn)
{
    extern __shared__ char smc[];
    __half* sQh = (__half*)(smc + OFF_QH);
    __half* sKh = (__half*)(smc + OFF_K);
    float*  sS  = (float*)(smc + OFF_S);
    __half* sP  = (__half*)(smc + OFF_P);
    float*  sM  = (float*)(smc + OFF_M);
    float*  sL  = (float*)(smc + OFF_L);
    float*  sA  = (float*)(smc + OFF_A);

    const int h     = blockIdx.x;
    const int ptile = (int)gridDim.y - 1 - blockIdx.y;
    const int m0    = ptile << 6;
    const int kvh   = h >> 3;
    const int tid   = threadIdx.x;
    const int wid   = tid >> 5;
    const int lane  = tid & 31;
    const int rs    = wid >> 1;      // 16-row slab / warp pair id
    const int ch    = wid & 1;
    const int pbar  = rs + 1;        // named barrier id for this pair
    const float scale = 0.08838834764831845f;

    float accO[8][4];
#pragma unroll
    for (int f = 0; f < 8; f++)
#pragma unroll
        for (int r = 0; r < 4; r++) accO[f][r] = 0.0f;

    auto load_kv = [&](int kb) {
        const int k0g = kb << 6;
        const uint32_t base = smem_u32(smc) + OFF_K;
#pragma unroll
        for (int i = 0; i < 4; i++) {
            int idx = tid + (i << 8);
            int r = idx >> 4, c = idx & 15;
            size_t so = (size_t)(k0g + r) * NKVD + kvh * HD + (c << 3);
            uint32_t off = r * (QLD * 2) + (c << 4);
            cpa16(base + off,         kh + so);
            cpa16(base + 17408 + off, vv + so);
        }
        CPA_COMMIT();
    };

    {
        uint32_t dqh = smem_u32(sQh);
#pragma unroll
        for (int i = 0; i < 4; i++) {
            int idx = tid + (i << 8);
            int r = idx >> 4, c = idx & 15;
            size_t so = (size_t)(m0 + r) * NQ + h * HD + (c << 3);
            uint32_t off = r * (QLD * 2) + (c << 4);
            cpa16(dqh + off, qh + so);
        }
        CPA_COMMIT();
    }
    if (tid < 64) { sM[tid] = -1e30f; sL[tid] = 0.f; }

    for (int kb = 0; kb <= ptile; kb++) {
        const int k0g = kb << 6;

        load_kv(kb);
        CPA_WAIT0();
        __syncthreads();

        // --- QK^T ---
        {
            wmma::fragment<wmma::accumulator, 16, 16, 16, float> accS[2];
            wmma::fill_fragment(accS[0], 0.0f);
            wmma::fill_fragment(accS[1], 0.0f);
#pragma unroll
            for (int k0 = 0; k0 < 128; k0 += 16) {
                wmma::fragment<wmma::matrix_a, 16, 16, 16, __half, wmma::row_major> ah;
                wmma::load_matrix_sync(ah, sQh + rs * 16 * QLD + k0, QLD);
#pragma unroll
                for (int j = 0; j < 2; j++) {
                    wmma::fragment<wmma::matrix_b, 16, 16, 16, __half, wmma::col_major> bh;
                    int kcol = ch * 32 + j * 16;
                    wmma::load_matrix_sync(bh, sKh + kcol * QLD + k0, QLD);
                    wmma::mma_sync(accS[j], ah, bh, accS[j]);
                }
            }
#pragma unroll
            for (int j = 0; j < 2; j++)
                wmma::store_matrix_sync(sS + rs * 16 * SLD + ch * 32 + j * 16,
                                        accS[j], SLD, wmma::mem_row_major);
        }
        BAR_PAIR(pbar);   // pair-scoped: scores block rs ready

        // --- online softmax (rows [wid*8, wid*8+8) c block rs) ---
        {
            const int r  = tid >> 2;
            const int q4 = tid & 3;
            float* srow = sS + r * SLD + q4 * 16;
            const int qglob = m0 + r;
            const int kbase = k0g + q4 * 16;

            float vals[16];
            float mx = -1e30f;
#pragma unroll
            for (int j = 0; j < 16; j++) {
                float s = srow[j];
                s = (kbase + j <= qglob) ? s * scale : -1e30f;
                vals[j] = s;
                mx = fmaxf(mx, s);
            }
            mx = fmaxf(mx, __shfl_xor_sync(0xffffffffu, mx, 1));
            mx = fmaxf(mx, __shfl_xor_sync(0xffffffffu, mx, 2));

            float mold = sM[r];
            float mnew = fmaxf(mold, mx);
            float alpha = fexp(mold - mnew);

            __half* prow = sP + r * PLD + q4 * 16;
            float lsum = 0.f;
#pragma unroll
            for (int j = 0; j < 16; j++) {
                float p = fexp(vals[j] - mnew);
                prow[j] = __float2half(p);
                lsum += p;
            }
            lsum += __shfl_xor_sync(0xffffffffu, lsum, 1);
            lsum += __shfl_xor_sync(0xffffffffu, lsum, 2);

            if (q4 == 0) {
                sM[r] = mnew;
                sL[r] = sL[r] * alpha + lsum;
                sA[r] = alpha;
            }
        }
        BAR_PAIR(pbar);   // pair-scoped: P block rs + alpha ready

        // --- rescale O (registers) and accumulate P @ V ---
        {
            const int qr = rs * 16 + (lane >> 2);
            const float a0 = sA[qr], a1 = sA[qr + 8];
#pragma unroll
            for (int f = 0; f < 8; f++) {
                accO[f][0] *= a0; accO[f][1] *= a0;
                accO[f][2] *= a1; accO[f][3] *= a1;
            }

            const uint32_t pA = smem_u32(smc) + OFF_P
                              + (rs * 16 + (lane & 15)) * (PLD * 2)
                              + ((lane >> 4) << 4);
            const uint32_t vB = smem_u32(smc) + OFF_V
                              + (lane & 15) * (QLD * 2)
                              + (ch * 64 + ((lane >> 4) << 3)) * 2;
#pragma unroll
            for (int kk = 0; kk < 4; kk++) {
                uint32_t pa[4];
                LDSM4(pa, pA + kk * 32);
                const uint32_t vk = vB + kk * 16 * (QLD * 2);
#pragma unroll
                for (int nf = 0; nf < 4; nf++) {
                    uint32_t bt[4];
                    LDSM4T(bt, vk + nf * 32);
                    mma16816f(accO[nf * 2],     pa, bt[0], bt[1]);
                    mma16816f(accO[nf * 2 + 1], pa, bt[2], bt[3]);
                }
            }
        }
        __syncthreads();   // CTA-wide: K/V reads done before next load_kv
    }

    // Epilogue
    {
        const int qr = rs * 16 + (lane >> 2);
        const float l0 = 1.0f / sL[qr], l1 = 1.0f / sL[qr + 8];
        const size_t r0 = (size_t)(m0 + qr) * NQ + h * HD;
        const size_t r1 = r0 + 8 * NQ;
#pragma unroll
        for (int f = 0; f < 8; f++) {
            const int col = ch * 64 + (f >> 1) * 16 + (f & 1) * 8 + (lane & 3) * 2;
            *(__half2*)(attn + r0 + col) = __halves2half2(
                __float2half(accO[f][0] * l0), __float2half(accO[f][1] * l0));
            *(__half2*)(attn + r1 + col) = __halves2half2(
                __float2half(accO[f][2] * l1), __float2half(accO[f][3] * l1));
        }
    }
}

// ---------------------------------------------------------------------------
extern "C" void kernel_launch(void* const* d_in, const int* in_sizes, int n_in,
                              void* d_out, int out_size)
{
    (void)in_sizes; (void)n_in; (void)out_size;
    const float* x  = (const float*)d_in[0];
    const float* wq = (const float*)d_in[1];
    const float* wk = (const float*)d_in[2];
    const float* wv = (const float*)d_in[3];
    const float* wo = (const float*)d_in[4];
    const float* qn = (const float*)d_in[5];
    const float* kn = (const float*)d_in[6];
    const float* cs = (const float*)d_in[7];
    const float* sn = (const float*)d_in[8];
    float* out = (float*)d_out;

    float* qkv;
    cudaGetSymbolAddress((void**)&qkv, g_qkv);

    __half *x16, *w16q, *w16k, *w16v, *wo16, *at16;
    cudaGetSymbolAddress((void**)&x16,  g_x16);
    cudaGetSymbolAddress((void**)&w16q, g_w16q);
    cudaGetSymbolAddress((void**)&w16k, g_w16k);
    cudaGetSymbolAddress((void**)&w16v, g_w16v);
    cudaGetSymbolAddress((void**)&wo16, g_wo16);
    cudaGetSymbolAddress((void**)&at16, g_at16);

    __half *q16h, *k16h, *v16;
    cudaGetSymbolAddress((void**)&q16h, g_q16h);
    cudaGetSymbolAddress((void**)&k16h, g_k16h);
    cudaGetSymbolAddress((void**)&v16,  g_v16);

    cudaFuncSetAttribute(gemm_mma_f16t,
                         cudaFuncAttributeMaxDynamicSharedMemorySize, GEMM_SMEM);
    cudaFuncSetAttribute(flash_wmma,
                         cudaFuncAttributeMaxDynamicSharedMemorySize, FLASH_SMEM);

    // One merged fp32 -> fp16 convert launch (x + 4 weight matrices)
    {
        const int c0 = S_LEN * HID / 4;
        const int c1 = HID * NQ / 4;
        const int c2 = HID * NKVD / 4;
        const int c3 = HID * NKVD / 4;
        const int c4 = NQ * HID / 4;
        const int total = c0 + c1 + c2 + c3 + c4;
        cvt_all<<<(total + 255) / 256, 256>>>(
            (const float4*)x,  (uint2*)x16,  c0,
            (const float4*)wq, (uint2*)w16q, c1,
            (const float4*)wk, (uint2*)w16k, c2,
            (const float4*)wv, (uint2*)w16v, c3,
            (const float4*)wo, (uint2*)wo16, c4);
    }

    // Fused QKV projection (V columns stream straight to fp16 v16)
    gemm_mma_f16t<<<dim3(NQKV / 128, S_LEN / 128), 256, GEMM_SMEM>>>(
        x16, w16q, w16k, w16v, NQ, NKVD, NQ, NKVD, qkv, v16, NQKV, HID);

    // RMSNorm + RoPE -> fp16
    rmsnorm_rope_f16<<<S_LEN * NH,  128>>>(qkv, 0,  qn, cs, sn, NH,  q16h);
    rmsnorm_rope_f16<<<S_LEN * NKV, 128>>>(qkv, NQ, kn, cs, sn, NKV, k16h);

    // Flash attention (2 CTAs/SM, O in registers, pair barriers) -> fp16
    flash_wmma<<<dim3(NH, S_LEN / 64), 256, FLASH_SMEM>>>(
        q16h, k16h, v16, at16);

    // Output projection
    gemm_mma_f16t<<<dim3(HID / 128, S_LEN / 128), 256, GEMM_SMEM>>>(
        at16, wo16, wo16, wo16, HID, HID, HID, HID, out, (half*)0, HID, NQ);
}